// round 10
// baseline (speedup 1.0000x reference)
#include <cuda_runtime.h>
#include <cuda_bf16.h>
#include <math.h>
#include <stdint.h>

// Problem constants
#define CB   4096     // batch B
#define CDIN 1024     // D_IN
#define CD   256      // D
#define CK   1024     // K clusters
#define CL   32768    // L queue_n rows
#define CKQ  4096     // K*Q_MULT queue_k rows
#define PS_N 8        // j-splits, LSE over queue_n (R5 value: long mainloops)
#define PP_N (PS_N*2)
#define PS_K 16       // j-splits, LSE over queue_k (128 CTAs = one full wave)
#define PP_K (PS_K*2)
#define INV_TEMP (1.0f/0.07f)

// ------------------------- scratch (__device__ globals; no runtime alloc) -------------------------
static __device__ __align__(16) float g_F1[CB*CD];
static __device__ __align__(16) float g_rawF[CB*CD];
static __device__ __align__(16) float g_L[CB*CK];
static __device__ __align__(16) float g_aggraw[CK*CD];
static __device__ __align__(16) float g_aggk1[CK*CD];
static __device__ __align__(16) float g_Cpart[8*CB*CD];   // split-K partials
static __device__ float g_norm1[CK];
static __device__ float g_norm2[CK];
static __device__ float g_lposN[CB];
static __device__ float g_lposK[CK];
static __device__ float g_pmN[CB*PP_N];
static __device__ float g_psN[CB*PP_N];
static __device__ float g_pmK[CK*PP_K];
static __device__ float g_psK[CK*PP_K];
// split-bf16 operand buffers (hi/lo pairs)
static __device__ __align__(16) __nv_bfloat16 g_xh[CB*CDIN];
static __device__ __align__(16) __nv_bfloat16 g_xl[CB*CDIN];
static __device__ __align__(16) __nv_bfloat16 g_wth[CD*CDIN];
static __device__ __align__(16) __nv_bfloat16 g_wtl[CD*CDIN];
static __device__ __align__(16) __nv_bfloat16 g_F1h[CB*CD];
static __device__ __align__(16) __nv_bfloat16 g_F1l[CB*CD];
static __device__ __align__(16) __nv_bfloat16 g_F2h[CB*CD];
static __device__ __align__(16) __nv_bfloat16 g_F2l[CB*CD];
static __device__ __align__(16) __nv_bfloat16 g_ctxh[CK*CD];
static __device__ __align__(16) __nv_bfloat16 g_ctxl[CK*CD];
static __device__ __align__(16) __nv_bfloat16 g_LTh[CK*CB];
static __device__ __align__(16) __nv_bfloat16 g_LTl[CK*CB];
static __device__ __align__(16) __nv_bfloat16 g_FTh[CD*CB];
static __device__ __align__(16) __nv_bfloat16 g_FTl[CD*CB];
static __device__ __align__(16) __nv_bfloat16 g_aggk1b[CK*CD];
static __device__ __align__(16) __nv_bfloat16 g_qnb[CL*CD];
static __device__ __align__(16) __nv_bfloat16 g_qkb[CKQ*CD];

// ------------------------- PTX helpers (sm_80-era only: compute_103 virtual arch!) -------------------------
__device__ __forceinline__ uint32_t smem_u32(const void* p) {
    uint32_t a;
    asm("{ .reg .u64 t; cvta.to.shared.u64 t, %1; cvt.u32.u64 %0, t; }" : "=r"(a) : "l"(p));
    return a;
}
__device__ __forceinline__ void cp16(uint32_t dst, const void* src) {
    asm volatile("cp.async.cg.shared.global [%0], [%1], 16;" :: "r"(dst), "l"(src));
}
#define CP_COMMIT() asm volatile("cp.async.commit_group;" ::: "memory")
#define CP_WAIT0()  asm volatile("cp.async.wait_group 0;" ::: "memory")

__device__ __forceinline__ void ldm_x4(uint32_t r[4], uint32_t addr) {
    asm volatile("ldmatrix.sync.aligned.m8n8.x4.shared.b16 {%0,%1,%2,%3}, [%4];"
                 : "=r"(r[0]), "=r"(r[1]), "=r"(r[2]), "=r"(r[3]) : "r"(addr));
}
__device__ __forceinline__ void mma_bf16(float c[4], const uint32_t a[4], uint32_t b0, uint32_t b1) {
    asm volatile("mma.sync.aligned.m16n8k16.row.col.f32.bf16.bf16.f32 "
                 "{%0,%1,%2,%3}, {%4,%5,%6,%7}, {%8,%9}, {%0,%1,%2,%3};"
                 : "+f"(c[0]), "+f"(c[1]), "+f"(c[2]), "+f"(c[3])
                 : "r"(a[0]), "r"(a[1]), "r"(a[2]), "r"(a[3]), "r"(b0), "r"(b1));
}

__device__ __forceinline__ float gumbelf(float u) {
    u = u * (1.0f - 2e-6f) + 1e-6f;
    return -logf(-logf(u));
}
__device__ __forceinline__ void split2(float v, __nv_bfloat16& h, __nv_bfloat16& l) {
    h = __float2bfloat16_rn(v);
    l = __float2bfloat16_rn(v - __bfloat162float(h));
}

// ------------------------- elementwise split / transpose-split -------------------------
__global__ void k_split(const float* __restrict__ in, __nv_bfloat16* __restrict__ hi,
                        __nv_bfloat16* __restrict__ lo) {
    int i = blockIdx.x*256 + threadIdx.x;
    float4 v = reinterpret_cast<const float4*>(in)[i];
    __nv_bfloat16 h[4], l[4];
    split2(v.x, h[0], l[0]); split2(v.y, h[1], l[1]);
    split2(v.z, h[2], l[2]); split2(v.w, h[3], l[3]);
    reinterpret_cast<uint2*>(hi)[i] = *reinterpret_cast<uint2*>(h);
    reinterpret_cast<uint2*>(lo)[i] = *reinterpret_cast<uint2*>(l);
}

// in [R,C] fp32 -> out hi/lo bf16 [C,R]
__global__ void k_tsplit(const float* __restrict__ in, __nv_bfloat16* __restrict__ hiT,
                         __nv_bfloat16* __restrict__ loT, int R, int C) {
    __shared__ float t[32][33];
    int c0 = blockIdx.x*32, r0 = blockIdx.y*32;
    int tx = threadIdx.x, ty = threadIdx.y;  // 32 x 8
    #pragma unroll
    for (int i = 0; i < 4; i++)
        t[ty + i*8][tx] = in[(size_t)(r0 + ty + i*8)*C + c0 + tx];
    __syncthreads();
    #pragma unroll
    for (int i = 0; i < 4; i++) {
        float v = t[tx][ty + i*8];
        __nv_bfloat16 h, l;
        split2(v, h, l);
        size_t o = (size_t)(c0 + ty + i*8)*R + r0 + tx;
        hiT[o] = h; loT[o] = l;
    }
}

// sum split-K partials
__global__ void k_reduce(const float* __restrict__ part, float* __restrict__ outp,
                         int MN, int ks) {
    int i = blockIdx.x*256 + threadIdx.x;
    float s = 0.0f;
    for (int z = 0; z < ks; z++) s += part[(size_t)z*MN + i];
    outp[i] = s;
}

// ------------------------- row l2norm (D=256): fp32 + hi/lo bf16 outputs, optional divisor -------------------------
__global__ void k_l2norm(const float* __restrict__ in, float* __restrict__ outf,
                         __nv_bfloat16* __restrict__ outhi, __nv_bfloat16* __restrict__ outlo,
                         const float* __restrict__ divisor) {
    int r = blockIdx.x, t = threadIdx.x;  // 64 threads
    __shared__ float sh[2];
    float4 v = reinterpret_cast<const float4*>(in)[r*64 + t];
    if (divisor) {
        float d = 1.0f / (divisor[r] + 1e-8f);
        v.x *= d; v.y *= d; v.z *= d; v.w *= d;
    }
    float ss = v.x*v.x + v.y*v.y + v.z*v.z + v.w*v.w;
    #pragma unroll
    for (int o = 16; o; o >>= 1) ss += __shfl_xor_sync(0xffffffffu, ss, o);
    if ((t & 31) == 0) sh[t >> 5] = ss;
    __syncthreads();
    float s = rsqrtf(fmaxf(sh[0] + sh[1], 1e-12f));
    v.x *= s; v.y *= s; v.z *= s; v.w *= s;
    if (outf) reinterpret_cast<float4*>(outf)[r*64 + t] = v;
    if (outhi) {
        __nv_bfloat16 h[4], l[4];
        split2(v.x, h[0], l[0]); split2(v.y, h[1], l[1]);
        split2(v.z, h[2], l[2]); split2(v.w, h[3], l[3]);
        reinterpret_cast<uint2*>(outhi)[r*64 + t] = *reinterpret_cast<uint2*>(h);
        if (outlo) reinterpret_cast<uint2*>(outlo)[r*64 + t] = *reinterpret_cast<uint2*>(l);
    }
}

// queue = l2norm(2*l2norm(queue_k) + qnoise), fused; plain bf16 output
__global__ void k_queue_combine(const float* __restrict__ qk, const float* __restrict__ noise,
                                __nv_bfloat16* __restrict__ outb) {
    int r = blockIdx.x, t = threadIdx.x;  // 64 threads
    __shared__ float sh[2];
    float4 v = reinterpret_cast<const float4*>(qk)[r*64 + t];
    float ss = v.x*v.x + v.y*v.y + v.z*v.z + v.w*v.w;
    #pragma unroll
    for (int o = 16; o; o >>= 1) ss += __shfl_xor_sync(0xffffffffu, ss, o);
    if ((t & 31) == 0) sh[t >> 5] = ss;
    __syncthreads();
    float s1 = 2.0f * rsqrtf(fmaxf(sh[0] + sh[1], 1e-12f));
    float4 n = reinterpret_cast<const float4*>(noise)[r*64 + t];
    float4 w = make_float4(v.x*s1 + n.x, v.y*s1 + n.y, v.z*s1 + n.z, v.w*s1 + n.w);
    __syncthreads();
    float ss2 = w.x*w.x + w.y*w.y + w.z*w.z + w.w*w.w;
    #pragma unroll
    for (int o = 16; o; o >>= 1) ss2 += __shfl_xor_sync(0xffffffffu, ss2, o);
    if ((t & 31) == 0) sh[t >> 5] = ss2;
    __syncthreads();
    float s2 = rsqrtf(fmaxf(sh[0] + sh[1], 1e-12f));
    w.x *= s2; w.y *= s2; w.z *= s2; w.w *= s2;
    __nv_bfloat162 lo2 = __floats2bfloat162_rn(w.x, w.y);
    __nv_bfloat162 hi2 = __floats2bfloat162_rn(w.z, w.w);
    uint2 u = make_uint2(*(uint32_t*)&lo2, *(uint32_t*)&hi2);
    reinterpret_cast<uint2*>(outb)[r*64 + t] = u;
}

// ------------------------- split-bf16 NT GEMM (validated R5) -------------------------
#define GT_RS    144u
#define GT_TILE  (128u*GT_RS)
#define GT_STAGE (4u*GT_TILE)
#define GT_SMEM  (2u*GT_STAGE)

__device__ __forceinline__ void gt_load(uint32_t dst, const __nv_bfloat16* src,
                                        int row0, int K, int kc) {
    int tid = threadIdx.x;
    #pragma unroll
    for (int i = 0; i < 4; i++) {
        int idx = tid + (i << 8);
        int row = idx >> 3;
        int cc = (idx & 7) << 3;
        cp16(dst + (uint32_t)row*GT_RS + (uint32_t)cc*2u,
             src + (size_t)(row0 + row)*K + kc + cc);
    }
}

__global__ void __launch_bounds__(256, 1) k_mma3(
    const __nv_bfloat16* __restrict__ Ah, const __nv_bfloat16* __restrict__ Al,
    const __nv_bfloat16* __restrict__ Bh, const __nv_bfloat16* __restrict__ Bl,
    float* __restrict__ C, int M, int N, int K, int ksplit)
{
    extern __shared__ char sm[];
    uint32_t base = (smem_u32(sm) + 127u) & ~127u;
    int tid = threadIdx.x, lane = tid & 31, w = tid >> 5;
    int mg = w & 3, ng = w >> 2;
    int m0 = blockIdx.x * 128, n0 = blockIdx.y * 128;
    int Klocal = K / ksplit, kbase = blockIdx.z * Klocal;
    float* out = C + (size_t)blockIdx.z * M * N;
    int lt = lane >> 3, lr = lane & 7;
    uint32_t aOff = (uint32_t)(mg*32 + (lt & 1)*8 + lr)*GT_RS + (uint32_t)((lt >> 1)*8)*2u;
    uint32_t bOff = (uint32_t)(ng*64 + (lt >> 1)*8 + lr)*GT_RS + (uint32_t)((lt & 1)*8)*2u;

    {
        uint32_t s0 = base;
        gt_load(s0 + 0u*GT_TILE, Ah, m0, K, kbase);
        gt_load(s0 + 1u*GT_TILE, Al, m0, K, kbase);
        gt_load(s0 + 2u*GT_TILE, Bh, n0, K, kbase);
        gt_load(s0 + 3u*GT_TILE, Bl, n0, K, kbase);
        CP_COMMIT();
    }

    float acc[2][8][4];
    #pragma unroll
    for (int mt = 0; mt < 2; mt++)
        #pragma unroll
        for (int nt = 0; nt < 8; nt++)
            #pragma unroll
            for (int c = 0; c < 4; c++) acc[mt][nt][c] = 0.0f;

    int nk = Klocal >> 6;
    for (int kc = 0; kc < nk; kc++) {
        CP_WAIT0();
        __syncthreads();
        if (kc + 1 < nk) {
            uint32_t sn = base + (uint32_t)((kc + 1) & 1)*GT_STAGE;
            int kn = kbase + (kc + 1)*64;
            gt_load(sn + 0u*GT_TILE, Ah, m0, K, kn);
            gt_load(sn + 1u*GT_TILE, Al, m0, K, kn);
            gt_load(sn + 2u*GT_TILE, Bh, n0, K, kn);
            gt_load(sn + 3u*GT_TILE, Bl, n0, K, kn);
            CP_COMMIT();
        }
        uint32_t st = base + (uint32_t)(kc & 1)*GT_STAGE;
        #pragma unroll
        for (int k0 = 0; k0 < 64; k0 += 16) {
            uint32_t a0h[4], a1h[4], a0l[4], a1l[4];
            ldm_x4(a0h, st + 0u*GT_TILE + aOff + (uint32_t)k0*2u);
            ldm_x4(a1h, st + 0u*GT_TILE + aOff + 16u*GT_RS + (uint32_t)k0*2u);
            ldm_x4(a0l, st + 1u*GT_TILE + aOff + (uint32_t)k0*2u);
            ldm_x4(a1l, st + 1u*GT_TILE + aOff + 16u*GT_RS + (uint32_t)k0*2u);
            #pragma unroll
            for (int np = 0; np < 4; np++) {
                uint32_t bh[4], bl[4];
                ldm_x4(bh, st + 2u*GT_TILE + bOff + (uint32_t)np*16u*GT_RS + (uint32_t)k0*2u);
                ldm_x4(bl, st + 3u*GT_TILE + bOff + (uint32_t)np*16u*GT_RS + (uint32_t)k0*2u);
                mma_bf16(acc[0][2*np+0], a0h, bh[0], bh[1]);
                mma_bf16(acc[0][2*np+1], a0h, bh[2], bh[3]);
                mma_bf16(acc[1][2*np+0], a1h, bh[0], bh[1]);
                mma_bf16(acc[1][2*np+1], a1h, bh[2], bh[3]);
                mma_bf16(acc[0][2*np+0], a0h, bl[0], bl[1]);
                mma_bf16(acc[0][2*np+1], a0h, bl[2], bl[3]);
                mma_bf16(acc[1][2*np+0], a1h, bl[0], bl[1]);
                mma_bf16(acc[1][2*np+1], a1h, bl[2], bl[3]);
                mma_bf16(acc[0][2*np+0], a0l, bh[0], bh[1]);
                mma_bf16(acc[0][2*np+1], a0l, bh[2], bh[3]);
                mma_bf16(acc[1][2*np+0], a1l, bh[0], bh[1]);
                mma_bf16(acc[1][2*np+1], a1l, bh[2], bh[3]);
            }
        }
    }

    int gid = lane >> 2, qc = (lane & 3) << 1;
    #pragma unroll
    for (int mt = 0; mt < 2; mt++) {
        #pragma unroll
        for (int nt = 0; nt < 8; nt++) {
            int r0 = m0 + mg*32 + mt*16 + gid;
            int c0 = n0 + ng*64 + nt*8 + qc;
            float2 v0 = make_float2(acc[mt][nt][0], acc[mt][nt][1]);
            float2 v1 = make_float2(acc[mt][nt][2], acc[mt][nt][3]);
            *reinterpret_cast<float2*>(&out[(size_t)r0*N + c0]) = v0;
            *reinterpret_cast<float2*>(&out[(size_t)(r0 + 8)*N + c0]) = v1;
        }
    }
}

// ------------------------- HMMA bf16 LSE, fixed-max epilogue -------------------------
// All rows unit-norm => |logit|*scale <= scale. Constant max FM = scale: no per-tile
// max tracking/rescale/shuffles. Quad-lane reduce once at the end.
#define RSB 528u
#define LSE_TILE_BYTES (128u*RSB)
#define LSE_SMEM (3u*LSE_TILE_BYTES + 128u)

__device__ __forceinline__ void lse_load_tile(uint32_t dstbase, const __nv_bfloat16* src) {
    int tid = threadIdx.x;
    #pragma unroll
    for (int i = 0; i < 16; i++) {
        int idx = tid + (i << 8);
        int row = idx >> 5;
        int c = idx & 31;
        cp16(dstbase + (uint32_t)row*RSB + (uint32_t)c*16u, src + row*256 + c*8);
    }
}

__global__ void __launch_bounds__(256, 1) k_lse_mma(
    const __nv_bfloat16* __restrict__ A, const __nv_bfloat16* __restrict__ Q,
    float* __restrict__ pm, float* __restrict__ ps, int jspan, int ppart, float scale)
{
    extern __shared__ char smem_raw[];
    uint32_t base = (smem_u32(smem_raw) + 127u) & ~127u;
    uint32_t aBase  = base;
    uint32_t qBase0 = base + LSE_TILE_BYTES;
    uint32_t qBase1 = base + 2u*LSE_TILE_BYTES;

    int tid = threadIdx.x;
    int lane = tid & 31, w = tid >> 5;
    int mg = w & 3;
    int ng = w >> 2;
    int m0 = blockIdx.x * 128;
    int jbase = blockIdx.y * jspan;
    int nj = jspan >> 7;

    int lt = lane >> 3, lr = lane & 7;
    uint32_t aAddr = aBase + (uint32_t)(mg*32 + (lt & 1)*8 + lr)*RSB + (uint32_t)((lt >> 1)*8)*2u;
    uint32_t qOff = (uint32_t)(ng*64 + (lt >> 1)*8 + lr)*RSB + (uint32_t)((lt & 1)*8)*2u;

    lse_load_tile(aBase, A + (size_t)m0*256);
    lse_load_tile(qBase0, Q + (size_t)jbase*256);
    CP_COMMIT();

    const float FM = scale;
    float srun[4] = {0.0f, 0.0f, 0.0f, 0.0f};

    for (int jt = 0; jt < nj; jt++) {
        CP_WAIT0();
        __syncthreads();
        if (jt + 1 < nj) {
            lse_load_tile((jt & 1) ? qBase0 : qBase1, Q + (size_t)(jbase + (jt+1)*128)*256);
            CP_COMMIT();
        }
        uint32_t qB = (jt & 1) ? qBase1 : qBase0;

        float acc[2][8][4];
        #pragma unroll
        for (int mt = 0; mt < 2; mt++)
            #pragma unroll
            for (int nt = 0; nt < 8; nt++)
                #pragma unroll
                for (int c = 0; c < 4; c++) acc[mt][nt][c] = 0.0f;

        #pragma unroll 4
        for (int k0 = 0; k0 < 256; k0 += 16) {
            uint32_t a0[4], a1[4];
            ldm_x4(a0, aAddr + (uint32_t)k0*2u);
            ldm_x4(a1, aAddr + 16u*RSB + (uint32_t)k0*2u);
            #pragma unroll
            for (int np = 0; np < 4; np++) {
                uint32_t b[4];
                ldm_x4(b, qB + qOff + (uint32_t)np*16u*RSB + (uint32_t)k0*2u);
                mma_bf16(acc[0][2*np+0], a0, b[0], b[1]);
                mma_bf16(acc[0][2*np+1], a0, b[2], b[3]);
                mma_bf16(acc[1][2*np+0], a1, b[0], b[1]);
                mma_bf16(acc[1][2*np+1], a1, b[2], b[3]);
            }
        }

        // fixed-max epilogue: pure per-thread exp accumulation
        #pragma unroll
        for (int mt = 0; mt < 2; mt++) {
            #pragma unroll
            for (int rh = 0; rh < 2; rh++) {
                int s = mt*2 + rh;
                float es = 0.0f;
                #pragma unroll
                for (int nt = 0; nt < 8; nt++) {
                    es += __expf(fmaf(acc[mt][nt][rh*2+0], scale, -FM));
                    es += __expf(fmaf(acc[mt][nt][rh*2+1], scale, -FM));
                }
                srun[s] += es;
            }
        }
    }

    #pragma unroll
    for (int s = 0; s < 4; s++) {
        srun[s] += __shfl_xor_sync(0xffffffffu, srun[s], 1);
        srun[s] += __shfl_xor_sync(0xffffffffu, srun[s], 2);
    }
    if ((lane & 3) == 0) {
        int gid = lane >> 2;
        int slot = blockIdx.y*2 + ng;
        #pragma unroll
        for (int mt = 0; mt < 2; mt++) {
            #pragma unroll
            for (int rh = 0; rh < 2; rh++) {
                int s = mt*2 + rh;
                int row = m0 + mg*32 + mt*16 + rh*8 + gid;
                pm[row*ppart + slot] = FM;
                ps[row*ppart + slot] = srun[s];
            }
        }
    }
}

// ------------------------- gumbel-softmax (soft, in-place) + hard argmax -------------------------
__global__ void k_softmax_gumbel(float* __restrict__ Lm, const float* __restrict__ uS,
                                 const float* __restrict__ uH, float* __restrict__ assignOut) {
    int b = blockIdx.x, t = threadIdx.x;
    __shared__ float sh[8];
    __shared__ float shv[8];
    __shared__ int shi[8];
    float4* L4 = reinterpret_cast<float4*>(Lm) + b*(CK/4);
    float4 l = L4[t];
    float4 us = (reinterpret_cast<const float4*>(uS) + b*(CK/4))[t];
    float4 uh = (reinterpret_cast<const float4*>(uH) + b*(CK/4))[t];
    float zs[4] = { (l.x + gumbelf(us.x))*2.0f, (l.y + gumbelf(us.y))*2.0f,
                    (l.z + gumbelf(us.z))*2.0f, (l.w + gumbelf(us.w))*2.0f };
    float zh[4] = { l.x + gumbelf(uh.x), l.y + gumbelf(uh.y),
                    l.z + gumbelf(uh.z), l.w + gumbelf(uh.w) };
    float vm = fmaxf(fmaxf(zs[0], zs[1]), fmaxf(zs[2], zs[3]));
    #pragma unroll
    for (int o = 16; o; o >>= 1) vm = fmaxf(vm, __shfl_xor_sync(0xffffffffu, vm, o));
    if ((t & 31) == 0) sh[t >> 5] = vm;
    __syncthreads();
    float bm = sh[0];
    #pragma unroll
    for (int i = 1; i < 8; i++) bm = fmaxf(bm, sh[i]);
    float e[4];
    float es = 0.0f;
    #pragma unroll
    for (int j = 0; j < 4; j++) { e[j] = __expf(zs[j] - bm); es += e[j]; }
    #pragma unroll
    for (int o = 16; o; o >>= 1) es += __shfl_xor_sync(0xffffffffu, es, o);
    __syncthreads();
    if ((t & 31) == 0) sh[t >> 5] = es;
    __syncthreads();
    float S = 0.0f;
    #pragma unroll
    for (int i = 0; i < 8; i++) S += sh[i];
    float inv = 1.0f / S;
    L4[t] = make_float4(e[0]*inv, e[1]*inv, e[2]*inv, e[3]*inv);
    float bv = zh[0]; int bi = t*4;
    #pragma unroll
    for (int j = 1; j < 4; j++) if (zh[j] > bv) { bv = zh[j]; bi = t*4 + j; }
    #pragma unroll
    for (int o = 16; o; o >>= 1) {
        float ov = __shfl_xor_sync(0xffffffffu, bv, o);
        int   oi = __shfl_xor_sync(0xffffffffu, bi, o);
        if (ov > bv || (ov == bv && oi < bi)) { bv = ov; bi = oi; }
    }
    if ((t & 31) == 0) { shv[t >> 5] = bv; shi[t >> 5] = bi; }
    __syncthreads();
    if (t == 0 && assignOut) {
        float fbv = shv[0]; int fbi = shi[0];
        #pragma unroll
        for (int i = 1; i < 8; i++)
            if (shv[i] > fbv || (shv[i] == fbv && shi[i] < fbi)) { fbv = shv[i]; fbi = shi[i]; }
        assignOut[b] = (float)fbi;
    }
}

// column sums of assign [CB, CK] -> norm[CK]
__global__ void k_colsum(const float* __restrict__ A, float* __restrict__ norm) {
    int col = blockIdx.x * 256 + threadIdx.x;
    float s0 = 0, s1 = 0, s2 = 0, s3 = 0;
    for (int b = 0; b < CB; b += 4) {
        s0 += A[(b+0)*CK + col];
        s1 += A[(b+1)*CK + col];
        s2 += A[(b+2)*CK + col];
        s3 += A[(b+3)*CK + col];
    }
    norm[col] = (s0 + s1) + (s2 + s3);
}

// per-row dot of two [R,256] matrices (l_pos)
__global__ void k_rowdot(const float* __restrict__ A, const float* __restrict__ Bv,
                         float* __restrict__ out) {
    int r = blockIdx.x, t = threadIdx.x;  // 32 threads
    const float4* a4 = reinterpret_cast<const float4*>(A) + r*64;
    const float4* b4 = reinterpret_cast<const float4*>(Bv) + r*64;
    float4 a = a4[t], b = b4[t];
    float s = a.x*b.x + a.y*b.y + a.z*b.z + a.w*b.w;
    a = a4[t + 32]; b = b4[t + 32];
    s += a.x*b.x + a.y*b.y + a.z*b.z + a.w*b.w;
    #pragma unroll
    for (int o = 16; o; o >>= 1) s += __shfl_xor_sync(0xffffffffu, s, o);
    if (t == 0) out[r] = s;
}

__device__ __forceinline__ float blockReduceSum1024(float v, float* sh) {
    int t = threadIdx.x;
    #pragma unroll
    for (int o = 16; o; o >>= 1) v += __shfl_xor_sync(0xffffffffu, v, o);
    if ((t & 31) == 0) sh[t >> 5] = v;
    __syncthreads();
    float s = 0.0f;
    if (t < 32) {
        s = sh[t];
        #pragma unroll
        for (int o = 16; o; o >>= 1) s += __shfl_xor_sync(0xffffffffu, s, o);
    }
    return s;
}

__global__ void k_final(const float* __restrict__ pmN, const float* __restrict__ psN,
                        const float* __restrict__ lposN,
                        const float* __restrict__ pmK, const float* __restrict__ psK,
                        const float* __restrict__ lposK,
                        float* __restrict__ outLoss, int ppN, int ppK) {
    int t = threadIdx.x;
    __shared__ float sh[32];
    float accN = 0.0f;
    for (int r = t; r < CB; r += 1024) {
        float lp = lposN[r] * INV_TEMP;
        float m = lp, s = 1.0f;
        for (int p = 0; p < ppN; p++) {
            float mp = pmN[r*ppN + p], sp = psN[r*ppN + p];
            float mn = fmaxf(m, mp);
            s = s * __expf(m - mn) + sp * __expf(mp - mn);
            m = mn;
        }
        accN += m + logf(s) - lp;
    }
    float sumN = blockReduceSum1024(accN, sh);
    __syncthreads();
    float accK = 0.0f;
    {
        int r = t;
        float lp = lposK[r] * INV_TEMP;
        float m = lp, s = 1.0f;
        for (int p = 0; p < ppK; p++) {
            float mp = pmK[r*ppK + p], sp = psK[r*ppK + p];
            float mn = fmaxf(m, mp);
            s = s * __expf(m - mn) + sp * __expf(mp - mn);
            m = mn;
        }
        accK = m + logf(s) - lp;
    }
    float sumK = blockReduceSum1024(accK, sh);
    if (t == 0) *outLoss = sumN / (float)CB + sumK / (float)CK;
}

// ------------------------- host launcher (exact R5 schedule) -------------------------
extern "C" void kernel_launch(void* const* d_in, const int* in_sizes, int n_in,
                              void* d_out, int out_size) {
    const float* x1       = (const float*)d_in[0];
    const float* x2       = (const float*)d_in[1];
    const float* W1       = (const float*)d_in[2];
    const float* W2       = (const float*)d_in[3];
    const float* context1 = (const float*)d_in[4];
    const float* context2 = (const float*)d_in[5];
    const float* queue_n  = (const float*)d_in[6];
    const float* queue_k  = (const float*)d_in[7];
    const float* u1a      = (const float*)d_in[8];
    const float* u1b      = (const float*)d_in[9];
    const float* u2a      = (const float*)d_in[10];
    const float* u2b      = (const float*)d_in[11];
    const float* qnoise   = (const float*)d_in[12];

    float* out       = (float*)d_out;
    float* outAssign = out;
    float* outF2     = out + CB;
    float* outAggk2  = outF2 + (size_t)CB*CD;
    float* outLoss   = outAggk2 + (size_t)CK*CD;

    float *pF1, *pRawF, *pL, *pAggraw, *pAggk1, *pCpart,
          *pNorm1, *pNorm2, *pLposN, *pLposK, *pPmN, *pPsN, *pPmK, *pPsK;
    __nv_bfloat16 *pXh, *pXl, *pWth, *pWtl, *pF1h, *pF1l, *pF2h, *pF2l,
                  *pCtxh, *pCtxl, *pLTh, *pLTl, *pFTh, *pFTl,
                  *pAggk1b, *pQnb, *pQkb;
    cudaGetSymbolAddress((void**)&pF1,     g_F1);
    cudaGetSymbolAddress((void**)&pRawF,   g_rawF);
    cudaGetSymbolAddress((void**)&pL,      g_L);
    cudaGetSymbolAddress((void**)&pAggraw, g_aggraw);
    cudaGetSymbolAddress((void**)&pAggk1,  g_aggk1);
    cudaGetSymbolAddress((void**)&pCpart,  g_Cpart);
    cudaGetSymbolAddress((void**)&pNorm1,  g_norm1);
    cudaGetSymbolAddress((void**)&pNorm2,  g_norm2);
    cudaGetSymbolAddress((void**)&pLposN,  g_lposN);
    cudaGetSymbolAddress((void**)&pLposK,  g_lposK);
    cudaGetSymbolAddress((void**)&pPmN,    g_pmN);
    cudaGetSymbolAddress((void**)&pPsN,    g_psN);
    cudaGetSymbolAddress((void**)&pPmK,    g_pmK);
    cudaGetSymbolAddress((void**)&pPsK,    g_psK);
    cudaGetSymbolAddress((void**)&pXh,     g_xh);
    cudaGetSymbolAddress((void**)&pXl,     g_xl);
    cudaGetSymbolAddress((void**)&pWth,    g_wth);
    cudaGetSymbolAddress((void**)&pWtl,    g_wtl);
    cudaGetSymbolAddress((void**)&pF1h,    g_F1h);
    cudaGetSymbolAddress((void**)&pF1l,    g_F1l);
    cudaGetSymbolAddress((void**)&pF2h,    g_F2h);
    cudaGetSymbolAddress((void**)&pF2l,    g_F2l);
    cudaGetSymbolAddress((void**)&pCtxh,   g_ctxh);
    cudaGetSymbolAddress((void**)&pCtxl,   g_ctxl);
    cudaGetSymbolAddress((void**)&pLTh,    g_LTh);
    cudaGetSymbolAddress((void**)&pLTl,    g_LTl);
    cudaGetSymbolAddress((void**)&pFTh,    g_FTh);
    cudaGetSymbolAddress((void**)&pFTl,    g_FTl);
    cudaGetSymbolAddress((void**)&pAggk1b, g_aggk1b);
    cudaGetSymbolAddress((void**)&pQnb,    g_qnb);
    cudaGetSymbolAddress((void**)&pQkb,    g_qkb);

    cudaFuncSetAttribute(k_lse_mma, cudaFuncAttributeMaxDynamicSharedMemorySize, LSE_SMEM);
    cudaFuncSetAttribute(k_mma3, cudaFuncAttributeMaxDynamicSharedMemorySize, GT_SMEM);

    dim3 t328(32, 8);

    // queues -> bf16 (LSE operands)
    k_l2norm<<<CL, 64>>>(queue_n, nullptr, pQnb, nullptr, nullptr);
    k_queue_combine<<<CKQ, 64>>>(queue_k, qnoise, pQkb);

    // ---- view 1 features: F1 = l2norm(x1 @ W1) ----
    k_tsplit<<<dim3(CD/32, CDIN/32), t328>>>(W1, pWth, pWtl, CDIN, CD);
    k_split<<<CB*CDIN/4/256, 256>>>(x1, pXh, pXl);
    k_mma3<<<dim3(CB/128, CD/128, 2), 256, GT_SMEM>>>(pXh, pXl, pWth, pWtl, pCpart, CB, CD, CDIN, 2);
    k_reduce<<<CB*CD/256, 256>>>(pCpart, pRawF, CB*CD, 2);
    k_l2norm<<<CB, 64>>>(pRawF, pF1, pF1h, pF1l, nullptr);

    // ---- view 2 features: F2 = l2norm(x2 @ W2) (output 1) ----
    k_tsplit<<<dim3(CD/32, CDIN/32), t328>>>(W2, pWth, pWtl, CDIN, CD);
    k_split<<<CB*CDIN/4/256, 256>>>(x2, pXh, pXl);
    k_mma3<<<dim3(CB/128, CD/128, 2), 256, GT_SMEM>>>(pXh, pXl, pWth, pWtl, pCpart, CB, CD, CDIN, 2);
    k_reduce<<<CB*CD/256, 256>>>(pCpart, pRawF, CB*CD, 2);
    k_l2norm<<<CB, 64>>>(pRawF, outF2, pF2h, pF2l, nullptr);

    // ---- view 1: logits -> softmax -> agg ----
    k_l2norm<<<CK, 64>>>(context1, nullptr, pCtxh, pCtxl, nullptr);
    k_mma3<<<dim3(CB/128, CK/128, 1), 256, GT_SMEM>>>(pF1h, pF1l, pCtxh, pCtxl, pL, CB, CK, CD, 1);
    k_softmax_gumbel<<<CB, 256>>>(pL, u1a, u1b, outAssign);
    k_colsum<<<CK/256, 256>>>(pL, pNorm1);
    k_tsplit<<<dim3(CK/32, CB/32), t328>>>(pL, pLTh, pLTl, CB, CK);
    k_tsplit<<<dim3(CD/32, CB/32), t328>>>(pF1, pFTh, pFTl, CB, CD);
    k_mma3<<<dim3(CK/128, CD/128, 8), 256, GT_SMEM>>>(pLTh, pLTl, pFTh, pFTl, pCpart, CK, CD, CB, 8);
    k_reduce<<<CK*CD/256, 256>>>(pCpart, pAggraw, CK*CD, 8);
    k_l2norm<<<CK, 64>>>(pAggraw, pAggk1, pAggk1b, nullptr, pNorm1);

    // ---- view 2: logits -> softmax -> agg (output 2) ----
    k_l2norm<<<CK, 64>>>(context2, nullptr, pCtxh, pCtxl, nullptr);
    k_mma3<<<dim3(CB/128, CK/128, 1), 256, GT_SMEM>>>(pF2h, pF2l, pCtxh, pCtxl, pL, CB, CK, CD, 1);
    k_softmax_gumbel<<<CB, 256>>>(pL, u2a, u2b, nullptr);
    k_colsum<<<CK/256, 256>>>(pL, pNorm2);
    k_tsplit<<<dim3(CK/32, CB/32), t328>>>(pL, pLTh, pLTl, CB, CK);
    k_tsplit<<<dim3(CD/32, CB/32), t328>>>(outF2, pFTh, pFTl, CB, CD);
    k_mma3<<<dim3(CK/128, CD/128, 8), 256, GT_SMEM>>>(pLTh, pLTl, pFTh, pFTl, pCpart, CK, CD, CB, 8);
    k_reduce<<<CK*CD/256, 256>>>(pCpart, pAggraw, CK*CD, 8);
    k_l2norm<<<CK, 64>>>(pAggraw, outAggk2, nullptr, nullptr, pNorm2);

    // positives (fp32)
    k_rowdot<<<CB, 32>>>(pF1, outF2, pLposN);
    k_rowdot<<<CK, 32>>>(pAggk1, outAggk2, pLposK);

    // HMMA streamed GEMM + fixed-max logsumexp over negatives
    k_lse_mma<<<dim3(CB/128, PS_N), 256, LSE_SMEM>>>(pF1h, pQnb, pPmN, pPsN, CL/PS_N, PP_N, INV_TEMP);
    k_lse_mma<<<dim3(CK/128, PS_K), 256, LSE_SMEM>>>(pAggk1b, pQkb, pPmK, pPsK, CKQ/PS_K, PP_K, INV_TEMP);

    // final scalar loss
    k_final<<<1, 1024>>>(pPmN, pPsN, pLposN, pPmK, pPsK, pLposK, outLoss, PP_N, PP_K);
}

// round 11
// speedup vs baseline: 1.4905x; 1.4905x over previous
#include <cuda_runtime.h>
#include <cuda_bf16.h>
#include <math.h>
#include <stdint.h>

// Problem constants
#define CB   4096     // batch B
#define CDIN 1024     // D_IN
#define CD   256      // D
#define CK   1024     // K clusters
#define CL   32768    // L queue_n rows
#define CKQ  4096     // K*Q_MULT queue_k rows
#define PSPLIT 8      // j-splits for LSE partials (R5 champion value)
#define PPART (PSPLIT*2)
#define INV_TEMP (1.0f/0.07f)

// ------------------------- scratch (__device__ globals; no runtime alloc) -------------------------
static __device__ __align__(16) float g_F1[CB*CD];
static __device__ __align__(16) float g_rawF[CB*CD];
static __device__ __align__(16) float g_L[CB*CK];
static __device__ __align__(16) float g_aggraw[CK*CD];
static __device__ __align__(16) float g_aggk1[CK*CD];
static __device__ __align__(16) float g_Cpart[8*CB*CD];   // split-K partials
static __device__ float g_norm1[CK];
static __device__ float g_norm2[CK];
static __device__ float g_lposN[CB];
static __device__ float g_lposK[CK];
static __device__ float g_pmN[CB*PPART];
static __device__ float g_psN[CB*PPART];
static __device__ float g_pmK[CK*PPART];
static __device__ float g_psK[CK*PPART];
// split-bf16 operand buffers (hi/lo pairs)
static __device__ __align__(16) __nv_bfloat16 g_xh[CB*CDIN];
static __device__ __align__(16) __nv_bfloat16 g_xl[CB*CDIN];
static __device__ __align__(16) __nv_bfloat16 g_wth[CD*CDIN];
static __device__ __align__(16) __nv_bfloat16 g_wtl[CD*CDIN];
static __device__ __align__(16) __nv_bfloat16 g_F1h[CB*CD];
static __device__ __align__(16) __nv_bfloat16 g_F1l[CB*CD];
static __device__ __align__(16) __nv_bfloat16 g_F2h[CB*CD];
static __device__ __align__(16) __nv_bfloat16 g_F2l[CB*CD];
static __device__ __align__(16) __nv_bfloat16 g_ctxh[CK*CD];
static __device__ __align__(16) __nv_bfloat16 g_ctxl[CK*CD];
static __device__ __align__(16) __nv_bfloat16 g_LTh[CK*CB];
static __device__ __align__(16) __nv_bfloat16 g_LTl[CK*CB];
static __device__ __align__(16) __nv_bfloat16 g_FTh[CD*CB];
static __device__ __align__(16) __nv_bfloat16 g_FTl[CD*CB];
static __device__ __align__(16) __nv_bfloat16 g_aggk1b[CK*CD];
static __device__ __align__(16) __nv_bfloat16 g_qnb[CL*CD];
static __device__ __align__(16) __nv_bfloat16 g_qkb[CKQ*CD];

// ------------------------- PTX helpers (sm_80-era only: compute_103 virtual arch!) -------------------------
__device__ __forceinline__ uint32_t smem_u32(const void* p) {
    uint32_t a;
    asm("{ .reg .u64 t; cvta.to.shared.u64 t, %1; cvt.u32.u64 %0, t; }" : "=r"(a) : "l"(p));
    return a;
}
__device__ __forceinline__ void cp16(uint32_t dst, const void* src) {
    asm volatile("cp.async.cg.shared.global [%0], [%1], 16;" :: "r"(dst), "l"(src));
}
#define CP_COMMIT() asm volatile("cp.async.commit_group;" ::: "memory")
#define CP_WAIT0()  asm volatile("cp.async.wait_group 0;" ::: "memory")

__device__ __forceinline__ void ldm_x4(uint32_t r[4], uint32_t addr) {
    asm volatile("ldmatrix.sync.aligned.m8n8.x4.shared.b16 {%0,%1,%2,%3}, [%4];"
                 : "=r"(r[0]), "=r"(r[1]), "=r"(r[2]), "=r"(r[3]) : "r"(addr));
}
__device__ __forceinline__ void mma_bf16(float c[4], const uint32_t a[4], uint32_t b0, uint32_t b1) {
    asm volatile("mma.sync.aligned.m16n8k16.row.col.f32.bf16.bf16.f32 "
                 "{%0,%1,%2,%3}, {%4,%5,%6,%7}, {%8,%9}, {%0,%1,%2,%3};"
                 : "+f"(c[0]), "+f"(c[1]), "+f"(c[2]), "+f"(c[3])
                 : "r"(a[0]), "r"(a[1]), "r"(a[2]), "r"(a[3]), "r"(b0), "r"(b1));
}

__device__ __forceinline__ float gumbelf(float u) {
    u = u * (1.0f - 2e-6f) + 1e-6f;
    return -logf(-logf(u));
}
__device__ __forceinline__ void split2(float v, __nv_bfloat16& h, __nv_bfloat16& l) {
    h = __float2bfloat16_rn(v);
    l = __float2bfloat16_rn(v - __bfloat162float(h));
}

// ------------------------- elementwise split / transpose-split -------------------------
__global__ void k_split(const float* __restrict__ in, __nv_bfloat16* __restrict__ hi,
                        __nv_bfloat16* __restrict__ lo) {
    int i = blockIdx.x*256 + threadIdx.x;
    float4 v = reinterpret_cast<const float4*>(in)[i];
    __nv_bfloat16 h[4], l[4];
    split2(v.x, h[0], l[0]); split2(v.y, h[1], l[1]);
    split2(v.z, h[2], l[2]); split2(v.w, h[3], l[3]);
    reinterpret_cast<uint2*>(hi)[i] = *reinterpret_cast<uint2*>(h);
    reinterpret_cast<uint2*>(lo)[i] = *reinterpret_cast<uint2*>(l);
}

// in [R,C] fp32 -> out hi/lo bf16 [C,R]
__global__ void k_tsplit(const float* __restrict__ in, __nv_bfloat16* __restrict__ hiT,
                         __nv_bfloat16* __restrict__ loT, int R, int C) {
    __shared__ float t[32][33];
    int c0 = blockIdx.x*32, r0 = blockIdx.y*32;
    int tx = threadIdx.x, ty = threadIdx.y;  // 32 x 8
    #pragma unroll
    for (int i = 0; i < 4; i++)
        t[ty + i*8][tx] = in[(size_t)(r0 + ty + i*8)*C + c0 + tx];
    __syncthreads();
    #pragma unroll
    for (int i = 0; i < 4; i++) {
        float v = t[tx][ty + i*8];
        __nv_bfloat16 h, l;
        split2(v, h, l);
        size_t o = (size_t)(c0 + ty + i*8)*R + r0 + tx;
        hiT[o] = h; loT[o] = l;
    }
}

// sum split-K partials
__global__ void k_reduce(const float* __restrict__ part, float* __restrict__ outp,
                         int MN, int ks) {
    int i = blockIdx.x*256 + threadIdx.x;
    float s = 0.0f;
    for (int z = 0; z < ks; z++) s += part[(size_t)z*MN + i];
    outp[i] = s;
}

// ------------------------- row l2norm (D=256): fp32 + hi/lo bf16 outputs, optional divisor -------------------------
__global__ void k_l2norm(const float* __restrict__ in, float* __restrict__ outf,
                         __nv_bfloat16* __restrict__ outhi, __nv_bfloat16* __restrict__ outlo,
                         const float* __restrict__ divisor) {
    int r = blockIdx.x, t = threadIdx.x;  // 64 threads
    __shared__ float sh[2];
    float4 v = reinterpret_cast<const float4*>(in)[r*64 + t];
    if (divisor) {
        float d = 1.0f / (divisor[r] + 1e-8f);
        v.x *= d; v.y *= d; v.z *= d; v.w *= d;
    }
    float ss = v.x*v.x + v.y*v.y + v.z*v.z + v.w*v.w;
    #pragma unroll
    for (int o = 16; o; o >>= 1) ss += __shfl_xor_sync(0xffffffffu, ss, o);
    if ((t & 31) == 0) sh[t >> 5] = ss;
    __syncthreads();
    float s = rsqrtf(fmaxf(sh[0] + sh[1], 1e-12f));
    v.x *= s; v.y *= s; v.z *= s; v.w *= s;
    if (outf) reinterpret_cast<float4*>(outf)[r*64 + t] = v;
    if (outhi) {
        __nv_bfloat16 h[4], l[4];
        split2(v.x, h[0], l[0]); split2(v.y, h[1], l[1]);
        split2(v.z, h[2], l[2]); split2(v.w, h[3], l[3]);
        reinterpret_cast<uint2*>(outhi)[r*64 + t] = *reinterpret_cast<uint2*>(h);
        if (outlo) reinterpret_cast<uint2*>(outlo)[r*64 + t] = *reinterpret_cast<uint2*>(l);
    }
}

// queue = l2norm(2*l2norm(queue_k) + qnoise), fused; plain bf16 output
__global__ void k_queue_combine(const float* __restrict__ qk, const float* __restrict__ noise,
                                __nv_bfloat16* __restrict__ outb) {
    int r = blockIdx.x, t = threadIdx.x;  // 64 threads
    __shared__ float sh[2];
    float4 v = reinterpret_cast<const float4*>(qk)[r*64 + t];
    float ss = v.x*v.x + v.y*v.y + v.z*v.z + v.w*v.w;
    #pragma unroll
    for (int o = 16; o; o >>= 1) ss += __shfl_xor_sync(0xffffffffu, ss, o);
    if ((t & 31) == 0) sh[t >> 5] = ss;
    __syncthreads();
    float s1 = 2.0f * rsqrtf(fmaxf(sh[0] + sh[1], 1e-12f));
    float4 n = reinterpret_cast<const float4*>(noise)[r*64 + t];
    float4 w = make_float4(v.x*s1 + n.x, v.y*s1 + n.y, v.z*s1 + n.z, v.w*s1 + n.w);
    __syncthreads();
    float ss2 = w.x*w.x + w.y*w.y + w.z*w.z + w.w*w.w;
    #pragma unroll
    for (int o = 16; o; o >>= 1) ss2 += __shfl_xor_sync(0xffffffffu, ss2, o);
    if ((t & 31) == 0) sh[t >> 5] = ss2;
    __syncthreads();
    float s2 = rsqrtf(fmaxf(sh[0] + sh[1], 1e-12f));
    w.x *= s2; w.y *= s2; w.z *= s2; w.w *= s2;
    __nv_bfloat162 lo2 = __floats2bfloat162_rn(w.x, w.y);
    __nv_bfloat162 hi2 = __floats2bfloat162_rn(w.z, w.w);
    uint2 u = make_uint2(*(uint32_t*)&lo2, *(uint32_t*)&hi2);
    reinterpret_cast<uint2*>(outb)[r*64 + t] = u;
}

// ------------------------- split-bf16 NT GEMM (validated R5) -------------------------
#define GT_RS    144u
#define GT_TILE  (128u*GT_RS)
#define GT_STAGE (4u*GT_TILE)
#define GT_SMEM  (2u*GT_STAGE)

__device__ __forceinline__ void gt_load(uint32_t dst, const __nv_bfloat16* src,
                                        int row0, int K, int kc) {
    int tid = threadIdx.x;
    #pragma unroll
    for (int i = 0; i < 4; i++) {
        int idx = tid + (i << 8);
        int row = idx >> 3;
        int cc = (idx & 7) << 3;
        cp16(dst + (uint32_t)row*GT_RS + (uint32_t)cc*2u,
             src + (size_t)(row0 + row)*K + kc + cc);
    }
}

__global__ void __launch_bounds__(256, 1) k_mma3(
    const __nv_bfloat16* __restrict__ Ah, const __nv_bfloat16* __restrict__ Al,
    const __nv_bfloat16* __restrict__ Bh, const __nv_bfloat16* __restrict__ Bl,
    float* __restrict__ C, int M, int N, int K, int ksplit)
{
    extern __shared__ char sm[];
    uint32_t base = (smem_u32(sm) + 127u) & ~127u;
    int tid = threadIdx.x, lane = tid & 31, w = tid >> 5;
    int mg = w & 3, ng = w >> 2;
    int m0 = blockIdx.x * 128, n0 = blockIdx.y * 128;
    int Klocal = K / ksplit, kbase = blockIdx.z * Klocal;
    float* out = C + (size_t)blockIdx.z * M * N;
    int lt = lane >> 3, lr = lane & 7;
    uint32_t aOff = (uint32_t)(mg*32 + (lt & 1)*8 + lr)*GT_RS + (uint32_t)((lt >> 1)*8)*2u;
    uint32_t bOff = (uint32_t)(ng*64 + (lt >> 1)*8 + lr)*GT_RS + (uint32_t)((lt & 1)*8)*2u;

    {
        uint32_t s0 = base;
        gt_load(s0 + 0u*GT_TILE, Ah, m0, K, kbase);
        gt_load(s0 + 1u*GT_TILE, Al, m0, K, kbase);
        gt_load(s0 + 2u*GT_TILE, Bh, n0, K, kbase);
        gt_load(s0 + 3u*GT_TILE, Bl, n0, K, kbase);
        CP_COMMIT();
    }

    float acc[2][8][4];
    #pragma unroll
    for (int mt = 0; mt < 2; mt++)
        #pragma unroll
        for (int nt = 0; nt < 8; nt++)
            #pragma unroll
            for (int c = 0; c < 4; c++) acc[mt][nt][c] = 0.0f;

    int nk = Klocal >> 6;
    for (int kc = 0; kc < nk; kc++) {
        CP_WAIT0();
        __syncthreads();
        if (kc + 1 < nk) {
            uint32_t sn = base + (uint32_t)((kc + 1) & 1)*GT_STAGE;
            int kn = kbase + (kc + 1)*64;
            gt_load(sn + 0u*GT_TILE, Ah, m0, K, kn);
            gt_load(sn + 1u*GT_TILE, Al, m0, K, kn);
            gt_load(sn + 2u*GT_TILE, Bh, n0, K, kn);
            gt_load(sn + 3u*GT_TILE, Bl, n0, K, kn);
            CP_COMMIT();
        }
        uint32_t st = base + (uint32_t)(kc & 1)*GT_STAGE;
        #pragma unroll
        for (int k0 = 0; k0 < 64; k0 += 16) {
            uint32_t a0h[4], a1h[4], a0l[4], a1l[4];
            ldm_x4(a0h, st + 0u*GT_TILE + aOff + (uint32_t)k0*2u);
            ldm_x4(a1h, st + 0u*GT_TILE + aOff + 16u*GT_RS + (uint32_t)k0*2u);
            ldm_x4(a0l, st + 1u*GT_TILE + aOff + (uint32_t)k0*2u);
            ldm_x4(a1l, st + 1u*GT_TILE + aOff + 16u*GT_RS + (uint32_t)k0*2u);
            #pragma unroll
            for (int np = 0; np < 4; np++) {
                uint32_t bh[4], bl[4];
                ldm_x4(bh, st + 2u*GT_TILE + bOff + (uint32_t)np*16u*GT_RS + (uint32_t)k0*2u);
                ldm_x4(bl, st + 3u*GT_TILE + bOff + (uint32_t)np*16u*GT_RS + (uint32_t)k0*2u);
                mma_bf16(acc[0][2*np+0], a0h, bh[0], bh[1]);
                mma_bf16(acc[0][2*np+1], a0h, bh[2], bh[3]);
                mma_bf16(acc[1][2*np+0], a1h, bh[0], bh[1]);
                mma_bf16(acc[1][2*np+1], a1h, bh[2], bh[3]);
                mma_bf16(acc[0][2*np+0], a0h, bl[0], bl[1]);
                mma_bf16(acc[0][2*np+1], a0h, bl[2], bl[3]);
                mma_bf16(acc[1][2*np+0], a1h, bl[0], bl[1]);
                mma_bf16(acc[1][2*np+1], a1h, bl[2], bl[3]);
                mma_bf16(acc[0][2*np+0], a0l, bh[0], bh[1]);
                mma_bf16(acc[0][2*np+1], a0l, bh[2], bh[3]);
                mma_bf16(acc[1][2*np+0], a1l, bh[0], bh[1]);
                mma_bf16(acc[1][2*np+1], a1l, bh[2], bh[3]);
            }
        }
    }

    int gid = lane >> 2, qc = (lane & 3) << 1;
    #pragma unroll
    for (int mt = 0; mt < 2; mt++) {
        #pragma unroll
        for (int nt = 0; nt < 8; nt++) {
            int r0 = m0 + mg*32 + mt*16 + gid;
            int c0 = n0 + ng*64 + nt*8 + qc;
            float2 v0 = make_float2(acc[mt][nt][0], acc[mt][nt][1]);
            float2 v1 = make_float2(acc[mt][nt][2], acc[mt][nt][3]);
            *reinterpret_cast<float2*>(&out[(size_t)r0*N + c0]) = v0;
            *reinterpret_cast<float2*>(&out[(size_t)(r0 + 8)*N + c0]) = v1;
        }
    }
}

// ------------------------- HMMA bf16 LSE, fixed-max epilogue -------------------------
// All rows unit-norm => |logit|*scale <= scale (+bf16 slack). Constant max FM = scale:
// no per-tile max tracking, no rescale, no per-tile shuffles. Quad-reduce once at end.
#define RSB 528u
#define LSE_TILE_BYTES (128u*RSB)
#define LSE_SMEM (3u*LSE_TILE_BYTES + 128u)

__device__ __forceinline__ void lse_load_tile(uint32_t dstbase, const __nv_bfloat16* src) {
    int tid = threadIdx.x;
    #pragma unroll
    for (int i = 0; i < 16; i++) {
        int idx = tid + (i << 8);
        int row = idx >> 5;
        int c = idx & 31;
        cp16(dstbase + (uint32_t)row*RSB + (uint32_t)c*16u, src + row*256 + c*8);
    }
}

__global__ void __launch_bounds__(256, 1) k_lse_mma(
    const __nv_bfloat16* __restrict__ A, const __nv_bfloat16* __restrict__ Q,
    float* __restrict__ pm, float* __restrict__ ps, int jspan, float scale)
{
    extern __shared__ char smem_raw[];
    uint32_t base = (smem_u32(smem_raw) + 127u) & ~127u;
    uint32_t aBase  = base;
    uint32_t qBase0 = base + LSE_TILE_BYTES;
    uint32_t qBase1 = base + 2u*LSE_TILE_BYTES;

    int tid = threadIdx.x;
    int lane = tid & 31, w = tid >> 5;
    int mg = w & 3;
    int ng = w >> 2;
    int m0 = blockIdx.x * 128;
    int jbase = blockIdx.y * jspan;
    int nj = jspan >> 7;

    int lt = lane >> 3, lr = lane & 7;
    uint32_t aAddr = aBase + (uint32_t)(mg*32 + (lt & 1)*8 + lr)*RSB + (uint32_t)((lt >> 1)*8)*2u;
    uint32_t qOff = (uint32_t)(ng*64 + (lt >> 1)*8 + lr)*RSB + (uint32_t)((lt & 1)*8)*2u;

    lse_load_tile(aBase, A + (size_t)m0*256);
    lse_load_tile(qBase0, Q + (size_t)jbase*256);
    CP_COMMIT();

    const float FM = scale;
    float srun[4] = {0.0f, 0.0f, 0.0f, 0.0f};

    for (int jt = 0; jt < nj; jt++) {
        CP_WAIT0();
        __syncthreads();
        if (jt + 1 < nj) {
            lse_load_tile((jt & 1) ? qBase0 : qBase1, Q + (size_t)(jbase + (jt+1)*128)*256);
            CP_COMMIT();
        }
        uint32_t qB = (jt & 1) ? qBase1 : qBase0;

        float acc[2][8][4];
        #pragma unroll
        for (int mt = 0; mt < 2; mt++)
            #pragma unroll
            for (int nt = 0; nt < 8; nt++)
                #pragma unroll
                for (int c = 0; c < 4; c++) acc[mt][nt][c] = 0.0f;

        #pragma unroll 4
        for (int k0 = 0; k0 < 256; k0 += 16) {
            uint32_t a0[4], a1[4];
            ldm_x4(a0, aAddr + (uint32_t)k0*2u);
            ldm_x4(a1, aAddr + 16u*RSB + (uint32_t)k0*2u);
            #pragma unroll
            for (int np = 0; np < 4; np++) {
                uint32_t b[4];
                ldm_x4(b, qB + qOff + (uint32_t)np*16u*RSB + (uint32_t)k0*2u);
                mma_bf16(acc[0][2*np+0], a0, b[0], b[1]);
                mma_bf16(acc[0][2*np+1], a0, b[2], b[3]);
                mma_bf16(acc[1][2*np+0], a1, b[0], b[1]);
                mma_bf16(acc[1][2*np+1], a1, b[2], b[3]);
            }
        }

        // fixed-max epilogue: pure per-thread exp accumulation
        #pragma unroll
        for (int mt = 0; mt < 2; mt++) {
            #pragma unroll
            for (int rh = 0; rh < 2; rh++) {
                int s = mt*2 + rh;
                float es = 0.0f;
                #pragma unroll
                for (int nt = 0; nt < 8; nt++) {
                    es += __expf(fmaf(acc[mt][nt][rh*2+0], scale, -FM));
                    es += __expf(fmaf(acc[mt][nt][rh*2+1], scale, -FM));
                }
                srun[s] += es;
            }
        }
    }

    #pragma unroll
    for (int s = 0; s < 4; s++) {
        srun[s] += __shfl_xor_sync(0xffffffffu, srun[s], 1);
        srun[s] += __shfl_xor_sync(0xffffffffu, srun[s], 2);
    }
    if ((lane & 3) == 0) {
        int gid = lane >> 2;
        int slot = blockIdx.y*2 + ng;
        #pragma unroll
        for (int mt = 0; mt < 2; mt++) {
            #pragma unroll
            for (int rh = 0; rh < 2; rh++) {
                int s = mt*2 + rh;
                int row = m0 + mg*32 + mt*16 + rh*8 + gid;
                pm[row*PPART + slot] = FM;
                ps[row*PPART + slot] = srun[s];
            }
        }
    }
}

// ------------------------- gumbel-softmax (soft, in-place) + hard argmax -------------------------
__global__ void k_softmax_gumbel(float* __restrict__ Lm, const float* __restrict__ uS,
                                 const float* __restrict__ uH, float* __restrict__ assignOut) {
    int b = blockIdx.x, t = threadIdx.x;
    __shared__ float sh[8];
    __shared__ float shv[8];
    __shared__ int shi[8];
    float4* L4 = reinterpret_cast<float4*>(Lm) + b*(CK/4);
    float4 l = L4[t];
    float4 us = (reinterpret_cast<const float4*>(uS) + b*(CK/4))[t];
    float4 uh = (reinterpret_cast<const float4*>(uH) + b*(CK/4))[t];
    float zs[4] = { (l.x + gumbelf(us.x))*2.0f, (l.y + gumbelf(us.y))*2.0f,
                    (l.z + gumbelf(us.z))*2.0f, (l.w + gumbelf(us.w))*2.0f };
    float zh[4] = { l.x + gumbelf(uh.x), l.y + gumbelf(uh.y),
                    l.z + gumbelf(uh.z), l.w + gumbelf(uh.w) };
    float vm = fmaxf(fmaxf(zs[0], zs[1]), fmaxf(zs[2], zs[3]));
    #pragma unroll
    for (int o = 16; o; o >>= 1) vm = fmaxf(vm, __shfl_xor_sync(0xffffffffu, vm, o));
    if ((t & 31) == 0) sh[t >> 5] = vm;
    __syncthreads();
    float bm = sh[0];
    #pragma unroll
    for (int i = 1; i < 8; i++) bm = fmaxf(bm, sh[i]);
    float e[4];
    float es = 0.0f;
    #pragma unroll
    for (int j = 0; j < 4; j++) { e[j] = __expf(zs[j] - bm); es += e[j]; }
    #pragma unroll
    for (int o = 16; o; o >>= 1) es += __shfl_xor_sync(0xffffffffu, es, o);
    __syncthreads();
    if ((t & 31) == 0) sh[t >> 5] = es;
    __syncthreads();
    float S = 0.0f;
    #pragma unroll
    for (int i = 0; i < 8; i++) S += sh[i];
    float inv = 1.0f / S;
    L4[t] = make_float4(e[0]*inv, e[1]*inv, e[2]*inv, e[3]*inv);
    float bv = zh[0]; int bi = t*4;
    #pragma unroll
    for (int j = 1; j < 4; j++) if (zh[j] > bv) { bv = zh[j]; bi = t*4 + j; }
    #pragma unroll
    for (int o = 16; o; o >>= 1) {
        float ov = __shfl_xor_sync(0xffffffffu, bv, o);
        int   oi = __shfl_xor_sync(0xffffffffu, bi, o);
        if (ov > bv || (ov == bv && oi < bi)) { bv = ov; bi = oi; }
    }
    if ((t & 31) == 0) { shv[t >> 5] = bv; shi[t >> 5] = bi; }
    __syncthreads();
    if (t == 0 && assignOut) {
        float fbv = shv[0]; int fbi = shi[0];
        #pragma unroll
        for (int i = 1; i < 8; i++)
            if (shv[i] > fbv || (shv[i] == fbv && shi[i] < fbi)) { fbv = shv[i]; fbi = shi[i]; }
        assignOut[b] = (float)fbi;
    }
}

// column sums of assign [CB, CK] -> norm[CK]
__global__ void k_colsum(const float* __restrict__ A, float* __restrict__ norm) {
    int col = blockIdx.x * 256 + threadIdx.x;
    float s0 = 0, s1 = 0, s2 = 0, s3 = 0;
    for (int b = 0; b < CB; b += 4) {
        s0 += A[(b+0)*CK + col];
        s1 += A[(b+1)*CK + col];
        s2 += A[(b+2)*CK + col];
        s3 += A[(b+3)*CK + col];
    }
    norm[col] = (s0 + s1) + (s2 + s3);
}

// per-row dot of two [R,256] matrices (l_pos)
__global__ void k_rowdot(const float* __restrict__ A, const float* __restrict__ Bv,
                         float* __restrict__ out) {
    int r = blockIdx.x, t = threadIdx.x;  // 32 threads
    const float4* a4 = reinterpret_cast<const float4*>(A) + r*64;
    const float4* b4 = reinterpret_cast<const float4*>(Bv) + r*64;
    float4 a = a4[t], b = b4[t];
    float s = a.x*b.x + a.y*b.y + a.z*b.z + a.w*b.w;
    a = a4[t + 32]; b = b4[t + 32];
    s += a.x*b.x + a.y*b.y + a.z*b.z + a.w*b.w;
    #pragma unroll
    for (int o = 16; o; o >>= 1) s += __shfl_xor_sync(0xffffffffu, s, o);
    if (t == 0) out[r] = s;
}

__device__ __forceinline__ float blockReduceSum1024(float v, float* sh) {
    int t = threadIdx.x;
    #pragma unroll
    for (int o = 16; o; o >>= 1) v += __shfl_xor_sync(0xffffffffu, v, o);
    if ((t & 31) == 0) sh[t >> 5] = v;
    __syncthreads();
    float s = 0.0f;
    if (t < 32) {
        s = sh[t];
        #pragma unroll
        for (int o = 16; o; o >>= 1) s += __shfl_xor_sync(0xffffffffu, s, o);
    }
    return s;
}

__global__ void k_final(const float* __restrict__ pmN, const float* __restrict__ psN,
                        const float* __restrict__ lposN,
                        const float* __restrict__ pmK, const float* __restrict__ psK,
                        const float* __restrict__ lposK,
                        float* __restrict__ outLoss) {
    int t = threadIdx.x;
    __shared__ float sh[32];
    float accN = 0.0f;
    for (int r = t; r < CB; r += 1024) {
        float lp = lposN[r] * INV_TEMP;
        float m = lp, s = 1.0f;
        #pragma unroll
        for (int p = 0; p < PPART; p++) {
            float mp = pmN[r*PPART + p], sp = psN[r*PPART + p];
            float mn = fmaxf(m, mp);
            s = s * __expf(m - mn) + sp * __expf(mp - mn);
            m = mn;
        }
        accN += m + logf(s) - lp;
    }
    float sumN = blockReduceSum1024(accN, sh);
    __syncthreads();
    float accK = 0.0f;
    {
        int r = t;
        float lp = lposK[r] * INV_TEMP;
        float m = lp, s = 1.0f;
        #pragma unroll
        for (int p = 0; p < PPART; p++) {
            float mp = pmK[r*PPART + p], sp = psK[r*PPART + p];
            float mn = fmaxf(m, mp);
            s = s * __expf(m - mn) + sp * __expf(mp - mn);
            m = mn;
        }
        accK = m + logf(s) - lp;
    }
    float sumK = blockReduceSum1024(accK, sh);
    if (t == 0) *outLoss = sumN / (float)CB + sumK / (float)CK;
}

// ------------------------- host launcher (exact R5 champion schedule) -------------------------
extern "C" void kernel_launch(void* const* d_in, const int* in_sizes, int n_in,
                              void* d_out, int out_size) {
    const float* x1       = (const float*)d_in[0];
    const float* x2       = (const float*)d_in[1];
    const float* W1       = (const float*)d_in[2];
    const float* W2       = (const float*)d_in[3];
    const float* context1 = (const float*)d_in[4];
    const float* context2 = (const float*)d_in[5];
    const float* queue_n  = (const float*)d_in[6];
    const float* queue_k  = (const float*)d_in[7];
    const float* u1a      = (const float*)d_in[8];
    const float* u1b      = (const float*)d_in[9];
    const float* u2a      = (const float*)d_in[10];
    const float* u2b      = (const float*)d_in[11];
    const float* qnoise   = (const float*)d_in[12];

    float* out       = (float*)d_out;
    float* outAssign = out;
    float* outF2     = out + CB;
    float* outAggk2  = outF2 + (size_t)CB*CD;
    float* outLoss   = outAggk2 + (size_t)CK*CD;

    float *pF1, *pRawF, *pL, *pAggraw, *pAggk1, *pCpart,
          *pNorm1, *pNorm2, *pLposN, *pLposK, *pPmN, *pPsN, *pPmK, *pPsK;
    __nv_bfloat16 *pXh, *pXl, *pWth, *pWtl, *pF1h, *pF1l, *pF2h, *pF2l,
                  *pCtxh, *pCtxl, *pLTh, *pLTl, *pFTh, *pFTl,
                  *pAggk1b, *pQnb, *pQkb;
    cudaGetSymbolAddress((void**)&pF1,     g_F1);
    cudaGetSymbolAddress((void**)&pRawF,   g_rawF);
    cudaGetSymbolAddress((void**)&pL,      g_L);
    cudaGetSymbolAddress((void**)&pAggraw, g_aggraw);
    cudaGetSymbolAddress((void**)&pAggk1,  g_aggk1);
    cudaGetSymbolAddress((void**)&pCpart,  g_Cpart);
    cudaGetSymbolAddress((void**)&pNorm1,  g_norm1);
    cudaGetSymbolAddress((void**)&pNorm2,  g_norm2);
    cudaGetSymbolAddress((void**)&pLposN,  g_lposN);
    cudaGetSymbolAddress((void**)&pLposK,  g_lposK);
    cudaGetSymbolAddress((void**)&pPmN,    g_pmN);
    cudaGetSymbolAddress((void**)&pPsN,    g_psN);
    cudaGetSymbolAddress((void**)&pPmK,    g_pmK);
    cudaGetSymbolAddress((void**)&pPsK,    g_psK);
    cudaGetSymbolAddress((void**)&pXh,     g_xh);
    cudaGetSymbolAddress((void**)&pXl,     g_xl);
    cudaGetSymbolAddress((void**)&pWth,    g_wth);
    cudaGetSymbolAddress((void**)&pWtl,    g_wtl);
    cudaGetSymbolAddress((void**)&pF1h,    g_F1h);
    cudaGetSymbolAddress((void**)&pF1l,    g_F1l);
    cudaGetSymbolAddress((void**)&pF2h,    g_F2h);
    cudaGetSymbolAddress((void**)&pF2l,    g_F2l);
    cudaGetSymbolAddress((void**)&pCtxh,   g_ctxh);
    cudaGetSymbolAddress((void**)&pCtxl,   g_ctxl);
    cudaGetSymbolAddress((void**)&pLTh,    g_LTh);
    cudaGetSymbolAddress((void**)&pLTl,    g_LTl);
    cudaGetSymbolAddress((void**)&pFTh,    g_FTh);
    cudaGetSymbolAddress((void**)&pFTl,    g_FTl);
    cudaGetSymbolAddress((void**)&pAggk1b, g_aggk1b);
    cudaGetSymbolAddress((void**)&pQnb,    g_qnb);
    cudaGetSymbolAddress((void**)&pQkb,    g_qkb);

    cudaFuncSetAttribute(k_lse_mma, cudaFuncAttributeMaxDynamicSharedMemorySize, LSE_SMEM);
    cudaFuncSetAttribute(k_mma3, cudaFuncAttributeMaxDynamicSharedMemorySize, GT_SMEM);

    dim3 t328(32, 8);

    // queues -> bf16 (LSE operands)
    k_l2norm<<<CL, 64>>>(queue_n, nullptr, pQnb, nullptr, nullptr);
    k_queue_combine<<<CKQ, 64>>>(queue_k, qnoise, pQkb);

    // ---- view 1 features: F1 = l2norm(x1 @ W1) ----
    k_tsplit<<<dim3(CD/32, CDIN/32), t328>>>(W1, pWth, pWtl, CDIN, CD);
    k_split<<<CB*CDIN/4/256, 256>>>(x1, pXh, pXl);
    k_mma3<<<dim3(CB/128, CD/128, 2), 256, GT_SMEM>>>(pXh, pXl, pWth, pWtl, pCpart, CB, CD, CDIN, 2);
    k_reduce<<<CB*CD/256, 256>>>(pCpart, pRawF, CB*CD, 2);
    k_l2norm<<<CB, 64>>>(pRawF, pF1, pF1h, pF1l, nullptr);

    // ---- view 2 features: F2 = l2norm(x2 @ W2) (output 1) ----
    k_tsplit<<<dim3(CD/32, CDIN/32), t328>>>(W2, pWth, pWtl, CDIN, CD);
    k_split<<<CB*CDIN/4/256, 256>>>(x2, pXh, pXl);
    k_mma3<<<dim3(CB/128, CD/128, 2), 256, GT_SMEM>>>(pXh, pXl, pWth, pWtl, pCpart, CB, CD, CDIN, 2);
    k_reduce<<<CB*CD/256, 256>>>(pCpart, pRawF, CB*CD, 2);
    k_l2norm<<<CB, 64>>>(pRawF, outF2, pF2h, pF2l, nullptr);

    // ---- view 1: logits -> softmax -> agg ----
    k_l2norm<<<CK, 64>>>(context1, nullptr, pCtxh, pCtxl, nullptr);
    k_mma3<<<dim3(CB/128, CK/128, 1), 256, GT_SMEM>>>(pF1h, pF1l, pCtxh, pCtxl, pL, CB, CK, CD, 1);
    k_softmax_gumbel<<<CB, 256>>>(pL, u1a, u1b, outAssign);
    k_colsum<<<CK/256, 256>>>(pL, pNorm1);
    k_tsplit<<<dim3(CK/32, CB/32), t328>>>(pL, pLTh, pLTl, CB, CK);
    k_tsplit<<<dim3(CD/32, CB/32), t328>>>(pF1, pFTh, pFTl, CB, CD);
    k_mma3<<<dim3(CK/128, CD/128, 8), 256, GT_SMEM>>>(pLTh, pLTl, pFTh, pFTl, pCpart, CK, CD, CB, 8);
    k_reduce<<<CK*CD/256, 256>>>(pCpart, pAggraw, CK*CD, 8);
    k_l2norm<<<CK, 64>>>(pAggraw, pAggk1, pAggk1b, nullptr, pNorm1);

    // ---- view 2: logits -> softmax -> agg (output 2) ----
    k_l2norm<<<CK, 64>>>(context2, nullptr, pCtxh, pCtxl, nullptr);
    k_mma3<<<dim3(CB/128, CK/128, 1), 256, GT_SMEM>>>(pF2h, pF2l, pCtxh, pCtxl, pL, CB, CK, CD, 1);
    k_softmax_gumbel<<<CB, 256>>>(pL, u2a, u2b, nullptr);
    k_colsum<<<CK/256, 256>>>(pL, pNorm2);
    k_tsplit<<<dim3(CK/32, CB/32), t328>>>(pL, pLTh, pLTl, CB, CK);
    k_tsplit<<<dim3(CD/32, CB/32), t328>>>(outF2, pFTh, pFTl, CB, CD);
    k_mma3<<<dim3(CK/128, CD/128, 8), 256, GT_SMEM>>>(pLTh, pLTl, pFTh, pFTl, pCpart, CK, CD, CB, 8);
    k_reduce<<<CK*CD/256, 256>>>(pCpart, pAggraw, CK*CD, 8);
    k_l2norm<<<CK, 64>>>(pAggraw, outAggk2, nullptr, nullptr, pNorm2);

    // positives (fp32)
    k_rowdot<<<CB, 32>>>(pF1, outF2, pLposN);
    k_rowdot<<<CK, 32>>>(pAggk1, outAggk2, pLposK);

    // HMMA streamed GEMM + fixed-max logsumexp over negatives
    k_lse_mma<<<dim3(CB/128, PSPLIT), 256, LSE_SMEM>>>(pF1h, pQnb, pPmN, pPsN, CL/PSPLIT, INV_TEMP);
    k_lse_mma<<<dim3(CK/128, PSPLIT), 256, LSE_SMEM>>>(pAggk1b, pQkb, pPmK, pPsK, CKQ/PSPLIT, INV_TEMP);

    // final scalar loss
    k_final<<<1, 1024>>>(pPmN, pPsN, pLposN, pPmK, pPsK, pLposK, outLoss);
}

// round 12
// speedup vs baseline: 2.0720x; 1.3901x over previous
#include <cuda_runtime.h>
#include <cuda_bf16.h>
#include <math.h>
#include <stdint.h>

// Problem constants
#define CB   4096     // batch B
#define CDIN 1024     // D_IN
#define CD   256      // D
#define CK   1024     // K clusters
#define CL   32768    // L queue_n rows
#define CKQ  4096     // K*Q_MULT queue_k rows
#define PSPLIT 8      // j-splits for LSE partials (champion value)
#define PPART (PSPLIT*2)
#define INV_TEMP (1.0f/0.07f)

// ------------------------- scratch (__device__ globals; no runtime alloc) -------------------------
static __device__ __align__(16) float g_F1[CB*CD];
static __device__ __align__(16) float g_L[CB*CK];
static __device__ __align__(16) float g_aggk1[CK*CD];
static __device__ __align__(16) float g_Cpart[8*CB*CD];   // split-K partials
static __device__ float g_lposN[CB];
static __device__ float g_lposK[CK];
static __device__ float g_pmN[CB*PPART];
static __device__ float g_psN[CB*PPART];
static __device__ float g_pmK[CK*PPART];
static __device__ float g_psK[CK*PPART];
// split-bf16 operand buffers (hi/lo pairs)
static __device__ __align__(16) __nv_bfloat16 g_xh[CB*CDIN];
static __device__ __align__(16) __nv_bfloat16 g_xl[CB*CDIN];
static __device__ __align__(16) __nv_bfloat16 g_wth[CD*CDIN];
static __device__ __align__(16) __nv_bfloat16 g_wtl[CD*CDIN];
static __device__ __align__(16) __nv_bfloat16 g_F1h[CB*CD];
static __device__ __align__(16) __nv_bfloat16 g_F1l[CB*CD];
static __device__ __align__(16) __nv_bfloat16 g_F2h[CB*CD];
static __device__ __align__(16) __nv_bfloat16 g_F2l[CB*CD];
static __device__ __align__(16) __nv_bfloat16 g_ctxh[CK*CD];
static __device__ __align__(16) __nv_bfloat16 g_ctxl[CK*CD];
static __device__ __align__(16) __nv_bfloat16 g_LTh[CK*CB];
static __device__ __align__(16) __nv_bfloat16 g_LTl[CK*CB];
static __device__ __align__(16) __nv_bfloat16 g_FTh[CD*CB];
static __device__ __align__(16) __nv_bfloat16 g_FTl[CD*CB];
static __device__ __align__(16) __nv_bfloat16 g_aggk1b[CK*CD];
static __device__ __align__(16) __nv_bfloat16 g_qnb[CL*CD];
static __device__ __align__(16) __nv_bfloat16 g_qkb[CKQ*CD];

// ------------------------- PTX helpers (sm_80-era only: compute_103 virtual arch!) -------------------------
__device__ __forceinline__ uint32_t smem_u32(const void* p) {
    uint32_t a;
    asm("{ .reg .u64 t; cvta.to.shared.u64 t, %1; cvt.u32.u64 %0, t; }" : "=r"(a) : "l"(p));
    return a;
}
__device__ __forceinline__ void cp16(uint32_t dst, const void* src) {
    asm volatile("cp.async.cg.shared.global [%0], [%1], 16;" :: "r"(dst), "l"(src));
}
#define CP_COMMIT() asm volatile("cp.async.commit_group;" ::: "memory")
#define CP_WAIT0()  asm volatile("cp.async.wait_group 0;" ::: "memory")

__device__ __forceinline__ void ldm_x4(uint32_t r[4], uint32_t addr) {
    asm volatile("ldmatrix.sync.aligned.m8n8.x4.shared.b16 {%0,%1,%2,%3}, [%4];"
                 : "=r"(r[0]), "=r"(r[1]), "=r"(r[2]), "=r"(r[3]) : "r"(addr));
}
__device__ __forceinline__ void mma_bf16(float c[4], const uint32_t a[4], uint32_t b0, uint32_t b1) {
    asm volatile("mma.sync.aligned.m16n8k16.row.col.f32.bf16.bf16.f32 "
                 "{%0,%1,%2,%3}, {%4,%5,%6,%7}, {%8,%9}, {%0,%1,%2,%3};"
                 : "+f"(c[0]), "+f"(c[1]), "+f"(c[2]), "+f"(c[3])
                 : "r"(a[0]), "r"(a[1]), "r"(a[2]), "r"(a[3]), "r"(b0), "r"(b1));
}

__device__ __forceinline__ float gumbelf(float u) {
    u = u * (1.0f - 2e-6f) + 1e-6f;
    return -logf(-logf(u));
}
__device__ __forceinline__ void split2(float v, __nv_bfloat16& h, __nv_bfloat16& l) {
    h = __float2bfloat16_rn(v);
    l = __float2bfloat16_rn(v - __bfloat162float(h));
}

// ------------------------- elementwise split / transpose-split -------------------------
__global__ void k_split(const float* __restrict__ in, __nv_bfloat16* __restrict__ hi,
                        __nv_bfloat16* __restrict__ lo) {
    int i = blockIdx.x*256 + threadIdx.x;
    float4 v = reinterpret_cast<const float4*>(in)[i];
    __nv_bfloat16 h[4], l[4];
    split2(v.x, h[0], l[0]); split2(v.y, h[1], l[1]);
    split2(v.z, h[2], l[2]); split2(v.w, h[3], l[3]);
    reinterpret_cast<uint2*>(hi)[i] = *reinterpret_cast<uint2*>(h);
    reinterpret_cast<uint2*>(lo)[i] = *reinterpret_cast<uint2*>(l);
}

// in [R,C] fp32 -> out hi/lo bf16 [C,R]
__global__ void k_tsplit(const float* __restrict__ in, __nv_bfloat16* __restrict__ hiT,
                         __nv_bfloat16* __restrict__ loT, int R, int C) {
    __shared__ float t[32][33];
    int c0 = blockIdx.x*32, r0 = blockIdx.y*32;
    int tx = threadIdx.x, ty = threadIdx.y;  // 32 x 8
    #pragma unroll
    for (int i = 0; i < 4; i++)
        t[ty + i*8][tx] = in[(size_t)(r0 + ty + i*8)*C + c0 + tx];
    __syncthreads();
    #pragma unroll
    for (int i = 0; i < 4; i++) {
        float v = t[tx][ty + i*8];
        __nv_bfloat16 h, l;
        split2(v, h, l);
        size_t o = (size_t)(c0 + ty + i*8)*R + r0 + tx;
        hiT[o] = h; loT[o] = l;
    }
}

// ------------------------- row l2norm (D=256) with fused split-K partial reduce -------------------------
// in = base of ks stacked partials of (mn4*4) floats each (ks=1: plain input).
// NOTE: no per-row divisor — l2norm is scale-invariant, so the reference's /normalizer is a no-op.
__global__ void k_l2norm(const float* __restrict__ in, int ks, int mn4,
                         float* __restrict__ outf,
                         __nv_bfloat16* __restrict__ outhi, __nv_bfloat16* __restrict__ outlo) {
    int r = blockIdx.x, t = threadIdx.x;  // 64 threads
    __shared__ float sh[2];
    int idx = r*64 + t;
    const float4* p = reinterpret_cast<const float4*>(in);
    float4 v = p[idx];
    for (int z = 1; z < ks; z++) {
        float4 w = p[(size_t)z*mn4 + idx];
        v.x += w.x; v.y += w.y; v.z += w.z; v.w += w.w;
    }
    float ss = v.x*v.x + v.y*v.y + v.z*v.z + v.w*v.w;
    #pragma unroll
    for (int o = 16; o; o >>= 1) ss += __shfl_xor_sync(0xffffffffu, ss, o);
    if ((t & 31) == 0) sh[t >> 5] = ss;
    __syncthreads();
    float s = rsqrtf(fmaxf(sh[0] + sh[1], 1e-12f));
    v.x *= s; v.y *= s; v.z *= s; v.w *= s;
    if (outf) reinterpret_cast<float4*>(outf)[idx] = v;
    if (outhi) {
        __nv_bfloat16 h[4], l[4];
        split2(v.x, h[0], l[0]); split2(v.y, h[1], l[1]);
        split2(v.z, h[2], l[2]); split2(v.w, h[3], l[3]);
        reinterpret_cast<uint2*>(outhi)[idx] = *reinterpret_cast<uint2*>(h);
        if (outlo) reinterpret_cast<uint2*>(outlo)[idx] = *reinterpret_cast<uint2*>(l);
    }
}

// queue = l2norm(2*l2norm(queue_k) + qnoise), fused; plain bf16 output
__global__ void k_queue_combine(const float* __restrict__ qk, const float* __restrict__ noise,
                                __nv_bfloat16* __restrict__ outb) {
    int r = blockIdx.x, t = threadIdx.x;  // 64 threads
    __shared__ float sh[2];
    float4 v = reinterpret_cast<const float4*>(qk)[r*64 + t];
    float ss = v.x*v.x + v.y*v.y + v.z*v.z + v.w*v.w;
    #pragma unroll
    for (int o = 16; o; o >>= 1) ss += __shfl_xor_sync(0xffffffffu, ss, o);
    if ((t & 31) == 0) sh[t >> 5] = ss;
    __syncthreads();
    float s1 = 2.0f * rsqrtf(fmaxf(sh[0] + sh[1], 1e-12f));
    float4 n = reinterpret_cast<const float4*>(noise)[r*64 + t];
    float4 w = make_float4(v.x*s1 + n.x, v.y*s1 + n.y, v.z*s1 + n.z, v.w*s1 + n.w);
    __syncthreads();
    float ss2 = w.x*w.x + w.y*w.y + w.z*w.z + w.w*w.w;
    #pragma unroll
    for (int o = 16; o; o >>= 1) ss2 += __shfl_xor_sync(0xffffffffu, ss2, o);
    if ((t & 31) == 0) sh[t >> 5] = ss2;
    __syncthreads();
    float s2 = rsqrtf(fmaxf(sh[0] + sh[1], 1e-12f));
    w.x *= s2; w.y *= s2; w.z *= s2; w.w *= s2;
    __nv_bfloat162 lo2 = __floats2bfloat162_rn(w.x, w.y);
    __nv_bfloat162 hi2 = __floats2bfloat162_rn(w.z, w.w);
    uint2 u = make_uint2(*(uint32_t*)&lo2, *(uint32_t*)&hi2);
    reinterpret_cast<uint2*>(outb)[r*64 + t] = u;
}

// ------------------------- split-bf16 NT GEMM (validated R5) -------------------------
#define GT_RS    144u
#define GT_TILE  (128u*GT_RS)
#define GT_STAGE (4u*GT_TILE)
#define GT_SMEM  (2u*GT_STAGE)

__device__ __forceinline__ void gt_load(uint32_t dst, const __nv_bfloat16* src,
                                        int row0, int K, int kc) {
    int tid = threadIdx.x;
    #pragma unroll
    for (int i = 0; i < 4; i++) {
        int idx = tid + (i << 8);
        int row = idx >> 3;
        int cc = (idx & 7) << 3;
        cp16(dst + (uint32_t)row*GT_RS + (uint32_t)cc*2u,
             src + (size_t)(row0 + row)*K + kc + cc);
    }
}

__global__ void __launch_bounds__(256, 1) k_mma3(
    const __nv_bfloat16* __restrict__ Ah, const __nv_bfloat16* __restrict__ Al,
    const __nv_bfloat16* __restrict__ Bh, const __nv_bfloat16* __restrict__ Bl,
    float* __restrict__ C, int M, int N, int K, int ksplit)
{
    extern __shared__ char sm[];
    uint32_t base = (smem_u32(sm) + 127u) & ~127u;
    int tid = threadIdx.x, lane = tid & 31, w = tid >> 5;
    int mg = w & 3, ng = w >> 2;
    int m0 = blockIdx.x * 128, n0 = blockIdx.y * 128;
    int Klocal = K / ksplit, kbase = blockIdx.z * Klocal;
    float* out = C + (size_t)blockIdx.z * M * N;
    int lt = lane >> 3, lr = lane & 7;
    uint32_t aOff = (uint32_t)(mg*32 + (lt & 1)*8 + lr)*GT_RS + (uint32_t)((lt >> 1)*8)*2u;
    uint32_t bOff = (uint32_t)(ng*64 + (lt >> 1)*8 + lr)*GT_RS + (uint32_t)((lt & 1)*8)*2u;

    {
        uint32_t s0 = base;
        gt_load(s0 + 0u*GT_TILE, Ah, m0, K, kbase);
        gt_load(s0 + 1u*GT_TILE, Al, m0, K, kbase);
        gt_load(s0 + 2u*GT_TILE, Bh, n0, K, kbase);
        gt_load(s0 + 3u*GT_TILE, Bl, n0, K, kbase);
        CP_COMMIT();
    }

    float acc[2][8][4];
    #pragma unroll
    for (int mt = 0; mt < 2; mt++)
        #pragma unroll
        for (int nt = 0; nt < 8; nt++)
            #pragma unroll
            for (int c = 0; c < 4; c++) acc[mt][nt][c] = 0.0f;

    int nk = Klocal >> 6;
    for (int kc = 0; kc < nk; kc++) {
        CP_WAIT0();
        __syncthreads();
        if (kc + 1 < nk) {
            uint32_t sn = base + (uint32_t)((kc + 1) & 1)*GT_STAGE;
            int kn = kbase + (kc + 1)*64;
            gt_load(sn + 0u*GT_TILE, Ah, m0, K, kn);
            gt_load(sn + 1u*GT_TILE, Al, m0, K, kn);
            gt_load(sn + 2u*GT_TILE, Bh, n0, K, kn);
            gt_load(sn + 3u*GT_TILE, Bl, n0, K, kn);
            CP_COMMIT();
        }
        uint32_t st = base + (uint32_t)(kc & 1)*GT_STAGE;
        #pragma unroll
        for (int k0 = 0; k0 < 64; k0 += 16) {
            uint32_t a0h[4], a1h[4], a0l[4], a1l[4];
            ldm_x4(a0h, st + 0u*GT_TILE + aOff + (uint32_t)k0*2u);
            ldm_x4(a1h, st + 0u*GT_TILE + aOff + 16u*GT_RS + (uint32_t)k0*2u);
            ldm_x4(a0l, st + 1u*GT_TILE + aOff + (uint32_t)k0*2u);
            ldm_x4(a1l, st + 1u*GT_TILE + aOff + 16u*GT_RS + (uint32_t)k0*2u);
            #pragma unroll
            for (int np = 0; np < 4; np++) {
                uint32_t bh[4], bl[4];
                ldm_x4(bh, st + 2u*GT_TILE + bOff + (uint32_t)np*16u*GT_RS + (uint32_t)k0*2u);
                ldm_x4(bl, st + 3u*GT_TILE + bOff + (uint32_t)np*16u*GT_RS + (uint32_t)k0*2u);
                mma_bf16(acc[0][2*np+0], a0h, bh[0], bh[1]);
                mma_bf16(acc[0][2*np+1], a0h, bh[2], bh[3]);
                mma_bf16(acc[1][2*np+0], a1h, bh[0], bh[1]);
                mma_bf16(acc[1][2*np+1], a1h, bh[2], bh[3]);
                mma_bf16(acc[0][2*np+0], a0h, bl[0], bl[1]);
                mma_bf16(acc[0][2*np+1], a0h, bl[2], bl[3]);
                mma_bf16(acc[1][2*np+0], a1h, bl[0], bl[1]);
                mma_bf16(acc[1][2*np+1], a1h, bl[2], bl[3]);
                mma_bf16(acc[0][2*np+0], a0l, bh[0], bh[1]);
                mma_bf16(acc[0][2*np+1], a0l, bh[2], bh[3]);
                mma_bf16(acc[1][2*np+0], a1l, bh[0], bh[1]);
                mma_bf16(acc[1][2*np+1], a1l, bh[2], bh[3]);
            }
        }
    }

    int gid = lane >> 2, qc = (lane & 3) << 1;
    #pragma unroll
    for (int mt = 0; mt < 2; mt++) {
        #pragma unroll
        for (int nt = 0; nt < 8; nt++) {
            int r0 = m0 + mg*32 + mt*16 + gid;
            int c0 = n0 + ng*64 + nt*8 + qc;
            float2 v0 = make_float2(acc[mt][nt][0], acc[mt][nt][1]);
            float2 v1 = make_float2(acc[mt][nt][2], acc[mt][nt][3]);
            *reinterpret_cast<float2*>(&out[(size_t)r0*N + c0]) = v0;
            *reinterpret_cast<float2*>(&out[(size_t)(r0 + 8)*N + c0]) = v1;
        }
    }
}

// ------------------------- HMMA bf16 LSE, fixed-max epilogue (validated R11) -------------------------
#define RSB 528u
#define LSE_TILE_BYTES (128u*RSB)
#define LSE_SMEM (3u*LSE_TILE_BYTES + 128u)

__device__ __forceinline__ void lse_load_tile(uint32_t dstbase, const __nv_bfloat16* src) {
    int tid = threadIdx.x;
    #pragma unroll
    for (int i = 0; i < 16; i++) {
        int idx = tid + (i << 8);
        int row = idx >> 5;
        int c = idx & 31;
        cp16(dstbase + (uint32_t)row*RSB + (uint32_t)c*16u, src + row*256 + c*8);
    }
}

__global__ void __launch_bounds__(256, 1) k_lse_mma(
    const __nv_bfloat16* __restrict__ A, const __nv_bfloat16* __restrict__ Q,
    float* __restrict__ pm, float* __restrict__ ps, int jspan, float scale)
{
    extern __shared__ char smem_raw[];
    uint32_t base = (smem_u32(smem_raw) + 127u) & ~127u;
    uint32_t aBase  = base;
    uint32_t qBase0 = base + LSE_TILE_BYTES;
    uint32_t qBase1 = base + 2u*LSE_TILE_BYTES;

    int tid = threadIdx.x;
    int lane = tid & 31, w = tid >> 5;
    int mg = w & 3;
    int ng = w >> 2;
    int m0 = blockIdx.x * 128;
    int jbase = blockIdx.y * jspan;
    int nj = jspan >> 7;

    int lt = lane >> 3, lr = lane & 7;
    uint32_t aAddr = aBase + (uint32_t)(mg*32 + (lt & 1)*8 + lr)*RSB + (uint32_t)((lt >> 1)*8)*2u;
    uint32_t qOff = (uint32_t)(ng*64 + (lt >> 1)*8 + lr)*RSB + (uint32_t)((lt & 1)*8)*2u;

    lse_load_tile(aBase, A + (size_t)m0*256);
    lse_load_tile(qBase0, Q + (size_t)jbase*256);
    CP_COMMIT();

    const float FM = scale;
    float srun[4] = {0.0f, 0.0f, 0.0f, 0.0f};

    for (int jt = 0; jt < nj; jt++) {
        CP_WAIT0();
        __syncthreads();
        if (jt + 1 < nj) {
            lse_load_tile((jt & 1) ? qBase0 : qBase1, Q + (size_t)(jbase + (jt+1)*128)*256);
            CP_COMMIT();
        }
        uint32_t qB = (jt & 1) ? qBase1 : qBase0;

        float acc[2][8][4];
        #pragma unroll
        for (int mt = 0; mt < 2; mt++)
            #pragma unroll
            for (int nt = 0; nt < 8; nt++)
                #pragma unroll
                for (int c = 0; c < 4; c++) acc[mt][nt][c] = 0.0f;

        #pragma unroll 4
        for (int k0 = 0; k0 < 256; k0 += 16) {
            uint32_t a0[4], a1[4];
            ldm_x4(a0, aAddr + (uint32_t)k0*2u);
            ldm_x4(a1, aAddr + 16u*RSB + (uint32_t)k0*2u);
            #pragma unroll
            for (int np = 0; np < 4; np++) {
                uint32_t b[4];
                ldm_x4(b, qB + qOff + (uint32_t)np*16u*RSB + (uint32_t)k0*2u);
                mma_bf16(acc[0][2*np+0], a0, b[0], b[1]);
                mma_bf16(acc[0][2*np+1], a0, b[2], b[3]);
                mma_bf16(acc[1][2*np+0], a1, b[0], b[1]);
                mma_bf16(acc[1][2*np+1], a1, b[2], b[3]);
            }
        }

        // fixed-max epilogue: pure per-thread exp accumulation
        #pragma unroll
        for (int mt = 0; mt < 2; mt++) {
            #pragma unroll
            for (int rh = 0; rh < 2; rh++) {
                int s = mt*2 + rh;
                float es = 0.0f;
                #pragma unroll
                for (int nt = 0; nt < 8; nt++) {
                    es += __expf(fmaf(acc[mt][nt][rh*2+0], scale, -FM));
                    es += __expf(fmaf(acc[mt][nt][rh*2+1], scale, -FM));
                }
                srun[s] += es;
            }
        }
    }

    #pragma unroll
    for (int s = 0; s < 4; s++) {
        srun[s] += __shfl_xor_sync(0xffffffffu, srun[s], 1);
        srun[s] += __shfl_xor_sync(0xffffffffu, srun[s], 2);
    }
    if ((lane & 3) == 0) {
        int gid = lane >> 2;
        int slot = blockIdx.y*2 + ng;
        #pragma unroll
        for (int mt = 0; mt < 2; mt++) {
            #pragma unroll
            for (int rh = 0; rh < 2; rh++) {
                int s = mt*2 + rh;
                int row = m0 + mg*32 + mt*16 + rh*8 + gid;
                pm[row*PPART + slot] = FM;
                ps[row*PPART + slot] = srun[s];
            }
        }
    }
}

// ------------------------- gumbel-softmax (soft, in-place) + hard argmax -------------------------
__global__ void k_softmax_gumbel(float* __restrict__ Lm, const float* __restrict__ uS,
                                 const float* __restrict__ uH, float* __restrict__ assignOut) {
    int b = blockIdx.x, t = threadIdx.x;
    __shared__ float sh[8];
    __shared__ float shv[8];
    __shared__ int shi[8];
    float4* L4 = reinterpret_cast<float4*>(Lm) + b*(CK/4);
    float4 l = L4[t];
    float4 us = (reinterpret_cast<const float4*>(uS) + b*(CK/4))[t];
    float4 uh = (reinterpret_cast<const float4*>(uH) + b*(CK/4))[t];
    float zs[4] = { (l.x + gumbelf(us.x))*2.0f, (l.y + gumbelf(us.y))*2.0f,
                    (l.z + gumbelf(us.z))*2.0f, (l.w + gumbelf(us.w))*2.0f };
    float zh[4] = { l.x + gumbelf(uh.x), l.y + gumbelf(uh.y),
                    l.z + gumbelf(uh.z), l.w + gumbelf(uh.w) };
    float vm = fmaxf(fmaxf(zs[0], zs[1]), fmaxf(zs[2], zs[3]));
    #pragma unroll
    for (int o = 16; o; o >>= 1) vm = fmaxf(vm, __shfl_xor_sync(0xffffffffu, vm, o));
    if ((t & 31) == 0) sh[t >> 5] = vm;
    __syncthreads();
    float bm = sh[0];
    #pragma unroll
    for (int i = 1; i < 8; i++) bm = fmaxf(bm, sh[i]);
    float e[4];
    float es = 0.0f;
    #pragma unroll
    for (int j = 0; j < 4; j++) { e[j] = __expf(zs[j] - bm); es += e[j]; }
    #pragma unroll
    for (int o = 16; o; o >>= 1) es += __shfl_xor_sync(0xffffffffu, es, o);
    __syncthreads();
    if ((t & 31) == 0) sh[t >> 5] = es;
    __syncthreads();
    float S = 0.0f;
    #pragma unroll
    for (int i = 0; i < 8; i++) S += sh[i];
    float inv = 1.0f / S;
    L4[t] = make_float4(e[0]*inv, e[1]*inv, e[2]*inv, e[3]*inv);
    float bv = zh[0]; int bi = t*4;
    #pragma unroll
    for (int j = 1; j < 4; j++) if (zh[j] > bv) { bv = zh[j]; bi = t*4 + j; }
    #pragma unroll
    for (int o = 16; o; o >>= 1) {
        float ov = __shfl_xor_sync(0xffffffffu, bv, o);
        int   oi = __shfl_xor_sync(0xffffffffu, bi, o);
        if (ov > bv || (ov == bv && oi < bi)) { bv = ov; bi = oi; }
    }
    if ((t & 31) == 0) { shv[t >> 5] = bv; shi[t >> 5] = bi; }
    __syncthreads();
    if (t == 0 && assignOut) {
        float fbv = shv[0]; int fbi = shi[0];
        #pragma unroll
        for (int i = 1; i < 8; i++)
            if (shv[i] > fbv || (shv[i] == fbv && shi[i] < fbi)) { fbv = shv[i]; fbi = shi[i]; }
        assignOut[b] = (float)fbi;
    }
}

// merged per-row dot: blocks [0,CB) -> lposN pair, [CB, CB+CK) -> lposK pair
__global__ void k_rowdot2(const float* __restrict__ A1, const float* __restrict__ B1,
                          float* __restrict__ o1,
                          const float* __restrict__ A2, const float* __restrict__ B2,
                          float* __restrict__ o2) {
    int r = blockIdx.x, t = threadIdx.x;  // 32 threads
    const float *Ap, *Bp;
    float* op;
    int rr;
    if (r < CB) { Ap = A1; Bp = B1; op = o1; rr = r; }
    else        { Ap = A2; Bp = B2; op = o2; rr = r - CB; }
    const float4* a4 = reinterpret_cast<const float4*>(Ap) + rr*64;
    const float4* b4 = reinterpret_cast<const float4*>(Bp) + rr*64;
    float4 a = a4[t], b = b4[t];
    float s = a.x*b.x + a.y*b.y + a.z*b.z + a.w*b.w;
    a = a4[t + 32]; b = b4[t + 32];
    s += a.x*b.x + a.y*b.y + a.z*b.z + a.w*b.w;
    #pragma unroll
    for (int o = 16; o; o >>= 1) s += __shfl_xor_sync(0xffffffffu, s, o);
    if (t == 0) op[rr] = s;
}

__device__ __forceinline__ float blockReduceSum1024(float v, float* sh) {
    int t = threadIdx.x;
    #pragma unroll
    for (int o = 16; o; o >>= 1) v += __shfl_xor_sync(0xffffffffu, v, o);
    if ((t & 31) == 0) sh[t >> 5] = v;
    __syncthreads();
    float s = 0.0f;
    if (t < 32) {
        s = sh[t];
        #pragma unroll
        for (int o = 16; o; o >>= 1) s += __shfl_xor_sync(0xffffffffu, s, o);
    }
    return s;
}

__global__ void k_final(const float* __restrict__ pmN, const float* __restrict__ psN,
                        const float* __restrict__ lposN,
                        const float* __restrict__ pmK, const float* __restrict__ psK,
                        const float* __restrict__ lposK,
                        float* __restrict__ outLoss) {
    int t = threadIdx.x;
    __shared__ float sh[32];
    float accN = 0.0f;
    for (int r = t; r < CB; r += 1024) {
        float lp = lposN[r] * INV_TEMP;
        float m = lp, s = 1.0f;
        #pragma unroll
        for (int p = 0; p < PPART; p++) {
            float mp = pmN[r*PPART + p], sp = psN[r*PPART + p];
            float mn = fmaxf(m, mp);
            s = s * __expf(m - mn) + sp * __expf(mp - mn);
            m = mn;
        }
        accN += m + logf(s) - lp;
    }
    float sumN = blockReduceSum1024(accN, sh);
    __syncthreads();
    float accK = 0.0f;
    {
        int r = t;
        float lp = lposK[r] * INV_TEMP;
        float m = lp, s = 1.0f;
        #pragma unroll
        for (int p = 0; p < PPART; p++) {
            float mp = pmK[r*PPART + p], sp = psK[r*PPART + p];
            float mn = fmaxf(m, mp);
            s = s * __expf(m - mn) + sp * __expf(mp - mn);
            m = mn;
        }
        accK = m + logf(s) - lp;
    }
    float sumK = blockReduceSum1024(accK, sh);
    if (t == 0) *outLoss = sumN / (float)CB + sumK / (float)CK;
}

// ------------------------- host launcher (champion schedule, slimmed) -------------------------
extern "C" void kernel_launch(void* const* d_in, const int* in_sizes, int n_in,
                              void* d_out, int out_size) {
    const float* x1       = (const float*)d_in[0];
    const float* x2       = (const float*)d_in[1];
    const float* W1       = (const float*)d_in[2];
    const float* W2       = (const float*)d_in[3];
    const float* context1 = (const float*)d_in[4];
    const float* context2 = (const float*)d_in[5];
    const float* queue_n  = (const float*)d_in[6];
    const float* queue_k  = (const float*)d_in[7];
    const float* u1a      = (const float*)d_in[8];
    const float* u1b      = (const float*)d_in[9];
    const float* u2a      = (const float*)d_in[10];
    const float* u2b      = (const float*)d_in[11];
    const float* qnoise   = (const float*)d_in[12];

    float* out       = (float*)d_out;
    float* outAssign = out;
    float* outF2     = out + CB;
    float* outAggk2  = outF2 + (size_t)CB*CD;
    float* outLoss   = outAggk2 + (size_t)CK*CD;

    float *pF1, *pL, *pAggk1, *pCpart,
          *pLposN, *pLposK, *pPmN, *pPsN, *pPmK, *pPsK;
    __nv_bfloat16 *pXh, *pXl, *pWth, *pWtl, *pF1h, *pF1l, *pF2h, *pF2l,
                  *pCtxh, *pCtxl, *pLTh, *pLTl, *pFTh, *pFTl,
                  *pAggk1b, *pQnb, *pQkb;
    cudaGetSymbolAddress((void**)&pF1,     g_F1);
    cudaGetSymbolAddress((void**)&pL,      g_L);
    cudaGetSymbolAddress((void**)&pAggk1,  g_aggk1);
    cudaGetSymbolAddress((void**)&pCpart,  g_Cpart);
    cudaGetSymbolAddress((void**)&pLposN,  g_lposN);
    cudaGetSymbolAddress((void**)&pLposK,  g_lposK);
    cudaGetSymbolAddress((void**)&pPmN,    g_pmN);
    cudaGetSymbolAddress((void**)&pPsN,    g_psN);
    cudaGetSymbolAddress((void**)&pPmK,    g_pmK);
    cudaGetSymbolAddress((void**)&pPsK,    g_psK);
    cudaGetSymbolAddress((void**)&pXh,     g_xh);
    cudaGetSymbolAddress((void**)&pXl,     g_xl);
    cudaGetSymbolAddress((void**)&pWth,    g_wth);
    cudaGetSymbolAddress((void**)&pWtl,    g_wtl);
    cudaGetSymbolAddress((void**)&pF1h,    g_F1h);
    cudaGetSymbolAddress((void**)&pF1l,    g_F1l);
    cudaGetSymbolAddress((void**)&pF2h,    g_F2h);
    cudaGetSymbolAddress((void**)&pF2l,    g_F2l);
    cudaGetSymbolAddress((void**)&pCtxh,   g_ctxh);
    cudaGetSymbolAddress((void**)&pCtxl,   g_ctxl);
    cudaGetSymbolAddress((void**)&pLTh,    g_LTh);
    cudaGetSymbolAddress((void**)&pLTl,    g_LTl);
    cudaGetSymbolAddress((void**)&pFTh,    g_FTh);
    cudaGetSymbolAddress((void**)&pFTl,    g_FTl);
    cudaGetSymbolAddress((void**)&pAggk1b, g_aggk1b);
    cudaGetSymbolAddress((void**)&pQnb,    g_qnb);
    cudaGetSymbolAddress((void**)&pQkb,    g_qkb);

    cudaFuncSetAttribute(k_lse_mma, cudaFuncAttributeMaxDynamicSharedMemorySize, LSE_SMEM);
    cudaFuncSetAttribute(k_mma3, cudaFuncAttributeMaxDynamicSharedMemorySize, GT_SMEM);

    dim3 t328(32, 8);
    const int MN4_FEAT = CB*CD/4;
    const int MN4_AGG  = CK*CD/4;

    // queues -> bf16 (LSE operands)
    k_l2norm<<<CL, 64>>>(queue_n, 1, 0, nullptr, pQnb, nullptr);
    k_queue_combine<<<CKQ, 64>>>(queue_k, qnoise, pQkb);

    // ---- view 1 features: F1 = l2norm(x1 @ W1) ----
    k_tsplit<<<dim3(CD/32, CDIN/32), t328>>>(W1, pWth, pWtl, CDIN, CD);
    k_split<<<CB*CDIN/4/256, 256>>>(x1, pXh, pXl);
    k_mma3<<<dim3(CB/128, CD/128, 2), 256, GT_SMEM>>>(pXh, pXl, pWth, pWtl, pCpart, CB, CD, CDIN, 2);
    k_l2norm<<<CB, 64>>>(pCpart, 2, MN4_FEAT, pF1, pF1h, pF1l);

    // ---- view 2 features: F2 = l2norm(x2 @ W2) (output 1) ----
    k_tsplit<<<dim3(CD/32, CDIN/32), t328>>>(W2, pWth, pWtl, CDIN, CD);
    k_split<<<CB*CDIN/4/256, 256>>>(x2, pXh, pXl);
    k_mma3<<<dim3(CB/128, CD/128, 2), 256, GT_SMEM>>>(pXh, pXl, pWth, pWtl, pCpart, CB, CD, CDIN, 2);
    k_l2norm<<<CB, 64>>>(pCpart, 2, MN4_FEAT, outF2, pF2h, pF2l);

    // ---- view 1: logits -> softmax -> agg (divisor dropped: l2norm is scale-invariant) ----
    k_l2norm<<<CK, 64>>>(context1, 1, 0, nullptr, pCtxh, pCtxl);
    k_mma3<<<dim3(CB/128, CK/128, 1), 256, GT_SMEM>>>(pF1h, pF1l, pCtxh, pCtxl, pL, CB, CK, CD, 1);
    k_softmax_gumbel<<<CB, 256>>>(pL, u1a, u1b, outAssign);
    k_tsplit<<<dim3(CK/32, CB/32), t328>>>(pL, pLTh, pLTl, CB, CK);
    k_tsplit<<<dim3(CD/32, CB/32), t328>>>(pF1, pFTh, pFTl, CB, CD);
    k_mma3<<<dim3(CK/128, CD/128, 8), 256, GT_SMEM>>>(pLTh, pLTl, pFTh, pFTl, pCpart, CK, CD, CB, 8);
    k_l2norm<<<CK, 64>>>(pCpart, 8, MN4_AGG, pAggk1, pAggk1b, nullptr);

    // ---- view 2: logits -> softmax -> agg (output 2) ----
    k_l2norm<<<CK, 64>>>(context2, 1, 0, nullptr, pCtxh, pCtxl);
    k_mma3<<<dim3(CB/128, CK/128, 1), 256, GT_SMEM>>>(pF2h, pF2l, pCtxh, pCtxl, pL, CB, CK, CD, 1);
    k_softmax_gumbel<<<CB, 256>>>(pL, u2a, u2b, nullptr);
    k_tsplit<<<dim3(CK/32, CB/32), t328>>>(pL, pLTh, pLTl, CB, CK);
    k_tsplit<<<dim3(CD/32, CB/32), t328>>>(outF2, pFTh, pFTl, CB, CD);
    k_mma3<<<dim3(CK/128, CD/128, 8), 256, GT_SMEM>>>(pLTh, pLTl, pFTh, pFTl, pCpart, CK, CD, CB, 8);
    k_l2norm<<<CK, 64>>>(pCpart, 8, MN4_AGG, outAggk2, nullptr, nullptr);

    // positives (fp32), merged
    k_rowdot2<<<CB + CK, 32>>>(pF1, outF2, pLposN, pAggk1, outAggk2, pLposK);

    // HMMA streamed GEMM + fixed-max logsumexp over negatives
    k_lse_mma<<<dim3(CB/128, PSPLIT), 256, LSE_SMEM>>>(pF1h, pQnb, pPmN, pPsN, CL/PSPLIT, INV_TEMP);
    k_lse_mma<<<dim3(CK/128, PSPLIT), 256, LSE_SMEM>>>(pAggk1b, pQkb, pPmK, pPsK, CKQ/PSPLIT, INV_TEMP);

    // final scalar loss
    k_final<<<1, 1024>>>(pPmN, pPsN, pLposN, pPmK, pPsK, pLposK, outLoss);
}

// round 13
// speedup vs baseline: 2.2117x; 1.0675x over previous
#include <cuda_runtime.h>
#include <cuda_bf16.h>
#include <math.h>
#include <stdint.h>

// Problem constants
#define CB   4096     // batch B
#define CDIN 1024     // D_IN
#define CD   256      // D
#define CK   1024     // K clusters
#define CL   32768    // L queue_n rows
#define CKQ  4096     // K*Q_MULT queue_k rows
#define PSPLIT 8      // j-splits for LSE partials (champion value)
#define PPART (PSPLIT*2)
#define INV_TEMP (1.0f/0.07f)

// ------------------------- scratch (__device__ globals; no runtime alloc) -------------------------
static __device__ __align__(16) float g_F1[CB*CD];
static __device__ __align__(16) float g_L[CB*CK];
static __device__ __align__(16) float g_L2[CB*CK];
static __device__ __align__(16) float g_aggk1[CK*CD];
static __device__ __align__(16) float g_Cpart[8*CB*CD];   // split-K partials (both views)
static __device__ float g_lposN[CB];
static __device__ float g_lposK[CK];
static __device__ float g_pmN[CB*PPART];
static __device__ float g_psN[CB*PPART];
static __device__ float g_pmK[CK*PPART];
static __device__ float g_psK[CK*PPART];
// split-bf16 operand buffers (hi/lo pairs), separate per view for batched launches
static __device__ __align__(16) __nv_bfloat16 g_xh[CB*CDIN],  g_xl[CB*CDIN];
static __device__ __align__(16) __nv_bfloat16 g_x2h[CB*CDIN], g_x2l[CB*CDIN];
static __device__ __align__(16) __nv_bfloat16 g_wth[CD*CDIN], g_wtl[CD*CDIN];
static __device__ __align__(16) __nv_bfloat16 g_wt2h[CD*CDIN],g_wt2l[CD*CDIN];
static __device__ __align__(16) __nv_bfloat16 g_F1h[CB*CD],  g_F1l[CB*CD];
static __device__ __align__(16) __nv_bfloat16 g_F2h[CB*CD],  g_F2l[CB*CD];
static __device__ __align__(16) __nv_bfloat16 g_ctx1h[CK*CD], g_ctx1l[CK*CD];
static __device__ __align__(16) __nv_bfloat16 g_ctx2h[CK*CD], g_ctx2l[CK*CD];
static __device__ __align__(16) __nv_bfloat16 g_LTh[CK*CB],  g_LTl[CK*CB];
static __device__ __align__(16) __nv_bfloat16 g_LT2h[CK*CB], g_LT2l[CK*CB];
static __device__ __align__(16) __nv_bfloat16 g_FTh[CD*CB],  g_FTl[CD*CB];
static __device__ __align__(16) __nv_bfloat16 g_FT2h[CD*CB], g_FT2l[CD*CB];
static __device__ __align__(16) __nv_bfloat16 g_aggk1b[CK*CD];
static __device__ __align__(16) __nv_bfloat16 g_qnb[CL*CD];
static __device__ __align__(16) __nv_bfloat16 g_qkb[CKQ*CD];

// ------------------------- PTX helpers (sm_80-era only: compute_103 virtual arch!) -------------------------
__device__ __forceinline__ uint32_t smem_u32(const void* p) {
    uint32_t a;
    asm("{ .reg .u64 t; cvta.to.shared.u64 t, %1; cvt.u32.u64 %0, t; }" : "=r"(a) : "l"(p));
    return a;
}
__device__ __forceinline__ void cp16(uint32_t dst, const void* src) {
    asm volatile("cp.async.cg.shared.global [%0], [%1], 16;" :: "r"(dst), "l"(src));
}
#define CP_COMMIT() asm volatile("cp.async.commit_group;" ::: "memory")
#define CP_WAIT0()  asm volatile("cp.async.wait_group 0;" ::: "memory")

__device__ __forceinline__ void ldm_x4(uint32_t r[4], uint32_t addr) {
    asm volatile("ldmatrix.sync.aligned.m8n8.x4.shared.b16 {%0,%1,%2,%3}, [%4];"
                 : "=r"(r[0]), "=r"(r[1]), "=r"(r[2]), "=r"(r[3]) : "r"(addr));
}
__device__ __forceinline__ void mma_bf16(float c[4], const uint32_t a[4], uint32_t b0, uint32_t b1) {
    asm volatile("mma.sync.aligned.m16n8k16.row.col.f32.bf16.bf16.f32 "
                 "{%0,%1,%2,%3}, {%4,%5,%6,%7}, {%8,%9}, {%0,%1,%2,%3};"
                 : "+f"(c[0]), "+f"(c[1]), "+f"(c[2]), "+f"(c[3])
                 : "r"(a[0]), "r"(a[1]), "r"(a[2]), "r"(a[3]), "r"(b0), "r"(b1));
}

__device__ __forceinline__ float gumbelf(float u) {
    u = u * (1.0f - 2e-6f) + 1e-6f;
    return -logf(-logf(u));
}
__device__ __forceinline__ void split2(float v, __nv_bfloat16& h, __nv_bfloat16& l) {
    h = __float2bfloat16_rn(v);
    l = __float2bfloat16_rn(v - __bfloat162float(h));
}

// ------------------------- batched split / transpose-split -------------------------
// two inputs of n4 float4 each
__global__ void k_split_b(const float* __restrict__ in1, __nv_bfloat16* __restrict__ hi1,
                          __nv_bfloat16* __restrict__ lo1,
                          const float* __restrict__ in2, __nv_bfloat16* __restrict__ hi2,
                          __nv_bfloat16* __restrict__ lo2, int n4) {
    int i = blockIdx.x*256 + threadIdx.x;
    const float* in = in1;
    __nv_bfloat16 *hi = hi1, *lo = lo1;
    if (i >= n4) { i -= n4; in = in2; hi = hi2; lo = lo2; }
    float4 v = reinterpret_cast<const float4*>(in)[i];
    __nv_bfloat16 h[4], l[4];
    split2(v.x, h[0], l[0]); split2(v.y, h[1], l[1]);
    split2(v.z, h[2], l[2]); split2(v.w, h[3], l[3]);
    reinterpret_cast<uint2*>(hi)[i] = *reinterpret_cast<uint2*>(h);
    reinterpret_cast<uint2*>(lo)[i] = *reinterpret_cast<uint2*>(l);
}

// two [R,C] fp32 inputs -> hi/lo bf16 [C,R] outputs; blockIdx.z selects the pair
__global__ void k_tsplit_b(const float* __restrict__ in1, __nv_bfloat16* __restrict__ hiT1,
                           __nv_bfloat16* __restrict__ loT1,
                           const float* __restrict__ in2, __nv_bfloat16* __restrict__ hiT2,
                           __nv_bfloat16* __restrict__ loT2, int R, int C) {
    __shared__ float t[32][33];
    const float* in = blockIdx.z ? in2 : in1;
    __nv_bfloat16* hiT = blockIdx.z ? hiT2 : hiT1;
    __nv_bfloat16* loT = blockIdx.z ? loT2 : loT1;
    int c0 = blockIdx.x*32, r0 = blockIdx.y*32;
    int tx = threadIdx.x, ty = threadIdx.y;  // 32 x 8
    #pragma unroll
    for (int i = 0; i < 4; i++)
        t[ty + i*8][tx] = in[(size_t)(r0 + ty + i*8)*C + c0 + tx];
    __syncthreads();
    #pragma unroll
    for (int i = 0; i < 4; i++) {
        float v = t[tx][ty + i*8];
        __nv_bfloat16 h, l;
        split2(v, h, l);
        size_t o = (size_t)(c0 + ty + i*8)*R + r0 + tx;
        hiT[o] = h; loT[o] = l;
    }
}

// ------------------------- batched row l2norm (D=256) with fused split-K reduce -------------------------
// rows [0,R1) -> set1, rows [R1, 2*R1) -> set2. No divisor (l2norm scale-invariant).
__global__ void k_l2norm_b(const float* __restrict__ in1, const float* __restrict__ in2,
                           int ks, int mn4, int R1,
                           float* __restrict__ outf1, __nv_bfloat16* __restrict__ outhi1,
                           __nv_bfloat16* __restrict__ outlo1,
                           float* __restrict__ outf2, __nv_bfloat16* __restrict__ outhi2,
                           __nv_bfloat16* __restrict__ outlo2) {
    int r = blockIdx.x, t = threadIdx.x;  // 64 threads
    __shared__ float sh[2];
    const float* in = in1;
    float* outf = outf1;
    __nv_bfloat16 *outhi = outhi1, *outlo = outlo1;
    if (r >= R1) { r -= R1; in = in2; outf = outf2; outhi = outhi2; outlo = outlo2; }
    int idx = r*64 + t;
    const float4* p = reinterpret_cast<const float4*>(in);
    float4 v = p[idx];
    for (int z = 1; z < ks; z++) {
        float4 w = p[(size_t)z*mn4 + idx];
        v.x += w.x; v.y += w.y; v.z += w.z; v.w += w.w;
    }
    float ss = v.x*v.x + v.y*v.y + v.z*v.z + v.w*v.w;
    #pragma unroll
    for (int o = 16; o; o >>= 1) ss += __shfl_xor_sync(0xffffffffu, ss, o);
    if ((t & 31) == 0) sh[t >> 5] = ss;
    __syncthreads();
    float s = rsqrtf(fmaxf(sh[0] + sh[1], 1e-12f));
    v.x *= s; v.y *= s; v.z *= s; v.w *= s;
    if (outf) reinterpret_cast<float4*>(outf)[idx] = v;
    if (outhi) {
        __nv_bfloat16 h[4], l[4];
        split2(v.x, h[0], l[0]); split2(v.y, h[1], l[1]);
        split2(v.z, h[2], l[2]); split2(v.w, h[3], l[3]);
        reinterpret_cast<uint2*>(outhi)[idx] = *reinterpret_cast<uint2*>(h);
        if (outlo) reinterpret_cast<uint2*>(outlo)[idx] = *reinterpret_cast<uint2*>(l);
    }
}

// queue = l2norm(2*l2norm(queue_k) + qnoise), fused; plain bf16 output
__global__ void k_queue_combine(const float* __restrict__ qk, const float* __restrict__ noise,
                                __nv_bfloat16* __restrict__ outb) {
    int r = blockIdx.x, t = threadIdx.x;  // 64 threads
    __shared__ float sh[2];
    float4 v = reinterpret_cast<const float4*>(qk)[r*64 + t];
    float ss = v.x*v.x + v.y*v.y + v.z*v.z + v.w*v.w;
    #pragma unroll
    for (int o = 16; o; o >>= 1) ss += __shfl_xor_sync(0xffffffffu, ss, o);
    if ((t & 31) == 0) sh[t >> 5] = ss;
    __syncthreads();
    float s1 = 2.0f * rsqrtf(fmaxf(sh[0] + sh[1], 1e-12f));
    float4 n = reinterpret_cast<const float4*>(noise)[r*64 + t];
    float4 w = make_float4(v.x*s1 + n.x, v.y*s1 + n.y, v.z*s1 + n.z, v.w*s1 + n.w);
    __syncthreads();
    float ss2 = w.x*w.x + w.y*w.y + w.z*w.z + w.w*w.w;
    #pragma unroll
    for (int o = 16; o; o >>= 1) ss2 += __shfl_xor_sync(0xffffffffu, ss2, o);
    if ((t & 31) == 0) sh[t >> 5] = ss2;
    __syncthreads();
    float s2 = rsqrtf(fmaxf(sh[0] + sh[1], 1e-12f));
    w.x *= s2; w.y *= s2; w.z *= s2; w.w *= s2;
    __nv_bfloat162 lo2 = __floats2bfloat162_rn(w.x, w.y);
    __nv_bfloat162 hi2 = __floats2bfloat162_rn(w.z, w.w);
    uint2 u = make_uint2(*(uint32_t*)&lo2, *(uint32_t*)&hi2);
    reinterpret_cast<uint2*>(outb)[r*64 + t] = u;
}

// ------------------------- split-bf16 NT GEMM, two-view batched (inner loop = validated R5) -------------------------
#define GT_RS    144u
#define GT_TILE  (128u*GT_RS)
#define GT_STAGE (4u*GT_TILE)
#define GT_SMEM  (2u*GT_STAGE)

__device__ __forceinline__ void gt_load(uint32_t dst, const __nv_bfloat16* src,
                                        int row0, int K, int kc) {
    int tid = threadIdx.x;
    #pragma unroll
    for (int i = 0; i < 4; i++) {
        int idx = tid + (i << 8);
        int row = idx >> 3;
        int cc = (idx & 7) << 3;
        cp16(dst + (uint32_t)row*GT_RS + (uint32_t)cc*2u,
             src + (size_t)(row0 + row)*K + kc + cc);
    }
}

__global__ void __launch_bounds__(256, 1) k_mma3_b(
    const __nv_bfloat16* __restrict__ A1h, const __nv_bfloat16* __restrict__ A1l,
    const __nv_bfloat16* __restrict__ B1h, const __nv_bfloat16* __restrict__ B1l,
    float* __restrict__ C1,
    const __nv_bfloat16* __restrict__ A2h, const __nv_bfloat16* __restrict__ A2l,
    const __nv_bfloat16* __restrict__ B2h, const __nv_bfloat16* __restrict__ B2l,
    float* __restrict__ C2,
    int M, int N, int K, int ksplit)
{
    extern __shared__ char sm[];
    uint32_t base = (smem_u32(sm) + 127u) & ~127u;
    int tid = threadIdx.x, lane = tid & 31, w = tid >> 5;
    int mg = w & 3, ng = w >> 2;
    int m0 = blockIdx.x * 128, n0 = blockIdx.y * 128;
    int z = blockIdx.z;
    const __nv_bfloat16 *Ah, *Al, *Bh, *Bl;
    float* Cb;
    if (z < ksplit) { Ah = A1h; Al = A1l; Bh = B1h; Bl = B1l; Cb = C1; }
    else            { Ah = A2h; Al = A2l; Bh = B2h; Bl = B2l; Cb = C2; z -= ksplit; }
    int Klocal = K / ksplit, kbase = z * Klocal;
    float* out = Cb + (size_t)z * M * N;
    int lt = lane >> 3, lr = lane & 7;
    uint32_t aOff = (uint32_t)(mg*32 + (lt & 1)*8 + lr)*GT_RS + (uint32_t)((lt >> 1)*8)*2u;
    uint32_t bOff = (uint32_t)(ng*64 + (lt >> 1)*8 + lr)*GT_RS + (uint32_t)((lt & 1)*8)*2u;

    {
        uint32_t s0 = base;
        gt_load(s0 + 0u*GT_TILE, Ah, m0, K, kbase);
        gt_load(s0 + 1u*GT_TILE, Al, m0, K, kbase);
        gt_load(s0 + 2u*GT_TILE, Bh, n0, K, kbase);
        gt_load(s0 + 3u*GT_TILE, Bl, n0, K, kbase);
        CP_COMMIT();
    }

    float acc[2][8][4];
    #pragma unroll
    for (int mt = 0; mt < 2; mt++)
        #pragma unroll
        for (int nt = 0; nt < 8; nt++)
            #pragma unroll
            for (int c = 0; c < 4; c++) acc[mt][nt][c] = 0.0f;

    int nk = Klocal >> 6;
    for (int kc = 0; kc < nk; kc++) {
        CP_WAIT0();
        __syncthreads();
        if (kc + 1 < nk) {
            uint32_t sn = base + (uint32_t)((kc + 1) & 1)*GT_STAGE;
            int kn = kbase + (kc + 1)*64;
            gt_load(sn + 0u*GT_TILE, Ah, m0, K, kn);
            gt_load(sn + 1u*GT_TILE, Al, m0, K, kn);
            gt_load(sn + 2u*GT_TILE, Bh, n0, K, kn);
            gt_load(sn + 3u*GT_TILE, Bl, n0, K, kn);
            CP_COMMIT();
        }
        uint32_t st = base + (uint32_t)(kc & 1)*GT_STAGE;
        #pragma unroll
        for (int k0 = 0; k0 < 64; k0 += 16) {
            uint32_t a0h[4], a1h[4], a0l[4], a1l[4];
            ldm_x4(a0h, st + 0u*GT_TILE + aOff + (uint32_t)k0*2u);
            ldm_x4(a1h, st + 0u*GT_TILE + aOff + 16u*GT_RS + (uint32_t)k0*2u);
            ldm_x4(a0l, st + 1u*GT_TILE + aOff + (uint32_t)k0*2u);
            ldm_x4(a1l, st + 1u*GT_TILE + aOff + 16u*GT_RS + (uint32_t)k0*2u);
            #pragma unroll
            for (int np = 0; np < 4; np++) {
                uint32_t bh[4], bl[4];
                ldm_x4(bh, st + 2u*GT_TILE + bOff + (uint32_t)np*16u*GT_RS + (uint32_t)k0*2u);
                ldm_x4(bl, st + 3u*GT_TILE + bOff + (uint32_t)np*16u*GT_RS + (uint32_t)k0*2u);
                mma_bf16(acc[0][2*np+0], a0h, bh[0], bh[1]);
                mma_bf16(acc[0][2*np+1], a0h, bh[2], bh[3]);
                mma_bf16(acc[1][2*np+0], a1h, bh[0], bh[1]);
                mma_bf16(acc[1][2*np+1], a1h, bh[2], bh[3]);
                mma_bf16(acc[0][2*np+0], a0h, bl[0], bl[1]);
                mma_bf16(acc[0][2*np+1], a0h, bl[2], bl[3]);
                mma_bf16(acc[1][2*np+0], a1h, bl[0], bl[1]);
                mma_bf16(acc[1][2*np+1], a1h, bl[2], bl[3]);
                mma_bf16(acc[0][2*np+0], a0l, bh[0], bh[1]);
                mma_bf16(acc[0][2*np+1], a0l, bh[2], bh[3]);
                mma_bf16(acc[1][2*np+0], a1l, bh[0], bh[1]);
                mma_bf16(acc[1][2*np+1], a1l, bh[2], bh[3]);
            }
        }
    }

    int gid = lane >> 2, qc = (lane & 3) << 1;
    #pragma unroll
    for (int mt = 0; mt < 2; mt++) {
        #pragma unroll
        for (int nt = 0; nt < 8; nt++) {
            int r0 = m0 + mg*32 + mt*16 + gid;
            int c0 = n0 + ng*64 + nt*8 + qc;
            float2 v0 = make_float2(acc[mt][nt][0], acc[mt][nt][1]);
            float2 v1 = make_float2(acc[mt][nt][2], acc[mt][nt][3]);
            *reinterpret_cast<float2*>(&out[(size_t)r0*N + c0]) = v0;
            *reinterpret_cast<float2*>(&out[(size_t)(r0 + 8)*N + c0]) = v1;
        }
    }
}

// ------------------------- HMMA bf16 LSE, fixed-max, two jobs merged in one launch -------------------------
#define RSB 528u
#define LSE_TILE_BYTES (128u*RSB)
#define LSE_SMEM (3u*LSE_TILE_BYTES + 128u)

__device__ __forceinline__ void lse_load_tile(uint32_t dstbase, const __nv_bfloat16* src) {
    int tid = threadIdx.x;
    #pragma unroll
    for (int i = 0; i < 16; i++) {
        int idx = tid + (i << 8);
        int row = idx >> 5;
        int c = idx & 31;
        cp16(dstbase + (uint32_t)row*RSB + (uint32_t)c*16u, src + row*256 + c*8);
    }
}

__global__ void __launch_bounds__(256, 1) k_lse2(
    const __nv_bfloat16* __restrict__ A1, const __nv_bfloat16* __restrict__ Q1,
    float* __restrict__ pm1, float* __restrict__ ps1, int jspan1, int nx1,
    const __nv_bfloat16* __restrict__ A2, const __nv_bfloat16* __restrict__ Q2,
    float* __restrict__ pm2, float* __restrict__ ps2, int jspan2, float scale)
{
    extern __shared__ char smem_raw[];
    uint32_t base = (smem_u32(smem_raw) + 127u) & ~127u;
    uint32_t aBase  = base;
    uint32_t qBase0 = base + LSE_TILE_BYTES;
    uint32_t qBase1 = base + 2u*LSE_TILE_BYTES;

    int bx = blockIdx.x;
    const __nv_bfloat16 *A, *Q;
    float *pm, *ps;
    int jspan;
    if (bx < nx1) { A = A1; Q = Q1; pm = pm1; ps = ps1; jspan = jspan1; }
    else          { A = A2; Q = Q2; pm = pm2; ps = ps2; jspan = jspan2; bx -= nx1; }

    int tid = threadIdx.x;
    int lane = tid & 31, w = tid >> 5;
    int mg = w & 3;
    int ng = w >> 2;
    int m0 = bx * 128;
    int jbase = blockIdx.y * jspan;
    int nj = jspan >> 7;

    int lt = lane >> 3, lr = lane & 7;
    uint32_t aAddr = aBase + (uint32_t)(mg*32 + (lt & 1)*8 + lr)*RSB + (uint32_t)((lt >> 1)*8)*2u;
    uint32_t qOff = (uint32_t)(ng*64 + (lt >> 1)*8 + lr)*RSB + (uint32_t)((lt & 1)*8)*2u;

    lse_load_tile(aBase, A + (size_t)m0*256);
    lse_load_tile(qBase0, Q + (size_t)jbase*256);
    CP_COMMIT();

    const float FM = scale;
    float srun[4] = {0.0f, 0.0f, 0.0f, 0.0f};

    for (int jt = 0; jt < nj; jt++) {
        CP_WAIT0();
        __syncthreads();
        if (jt + 1 < nj) {
            lse_load_tile((jt & 1) ? qBase0 : qBase1, Q + (size_t)(jbase + (jt+1)*128)*256);
            CP_COMMIT();
        }
        uint32_t qB = (jt & 1) ? qBase1 : qBase0;

        float acc[2][8][4];
        #pragma unroll
        for (int mt = 0; mt < 2; mt++)
            #pragma unroll
            for (int nt = 0; nt < 8; nt++)
                #pragma unroll
                for (int c = 0; c < 4; c++) acc[mt][nt][c] = 0.0f;

        #pragma unroll 4
        for (int k0 = 0; k0 < 256; k0 += 16) {
            uint32_t a0[4], a1[4];
            ldm_x4(a0, aAddr + (uint32_t)k0*2u);
            ldm_x4(a1, aAddr + 16u*RSB + (uint32_t)k0*2u);
            #pragma unroll
            for (int np = 0; np < 4; np++) {
                uint32_t b[4];
                ldm_x4(b, qB + qOff + (uint32_t)np*16u*RSB + (uint32_t)k0*2u);
                mma_bf16(acc[0][2*np+0], a0, b[0], b[1]);
                mma_bf16(acc[0][2*np+1], a0, b[2], b[3]);
                mma_bf16(acc[1][2*np+0], a1, b[0], b[1]);
                mma_bf16(acc[1][2*np+1], a1, b[2], b[3]);
            }
        }

        // fixed-max epilogue
        #pragma unroll
        for (int mt = 0; mt < 2; mt++) {
            #pragma unroll
            for (int rh = 0; rh < 2; rh++) {
                int s = mt*2 + rh;
                float es = 0.0f;
                #pragma unroll
                for (int nt = 0; nt < 8; nt++) {
                    es += __expf(fmaf(acc[mt][nt][rh*2+0], scale, -FM));
                    es += __expf(fmaf(acc[mt][nt][rh*2+1], scale, -FM));
                }
                srun[s] += es;
            }
        }
    }

    #pragma unroll
    for (int s = 0; s < 4; s++) {
        srun[s] += __shfl_xor_sync(0xffffffffu, srun[s], 1);
        srun[s] += __shfl_xor_sync(0xffffffffu, srun[s], 2);
    }
    if ((lane & 3) == 0) {
        int gid = lane >> 2;
        int slot = blockIdx.y*2 + ng;
        #pragma unroll
        for (int mt = 0; mt < 2; mt++) {
            #pragma unroll
            for (int rh = 0; rh < 2; rh++) {
                int s = mt*2 + rh;
                int row = m0 + mg*32 + mt*16 + rh*8 + gid;
                pm[row*PPART + slot] = FM;
                ps[row*PPART + slot] = srun[s];
            }
        }
    }
}

// ------------------------- batched gumbel-softmax (both views, one launch) -------------------------
__global__ void k_softmax_b(float* __restrict__ L1, const float* __restrict__ u1S,
                            const float* __restrict__ u1H, float* __restrict__ assignOut,
                            float* __restrict__ L2v, const float* __restrict__ u2S,
                            const float* __restrict__ u2H) {
    int b = blockIdx.x, t = threadIdx.x;
    float* Lm;
    const float *uS, *uH;
    float* aOut;
    if (b < CB) { Lm = L1; uS = u1S; uH = u1H; aOut = assignOut; }
    else        { b -= CB; Lm = L2v; uS = u2S; uH = u2H; aOut = nullptr; }
    __shared__ float sh[8];
    __shared__ float shv[8];
    __shared__ int shi[8];
    float4* L4 = reinterpret_cast<float4*>(Lm) + b*(CK/4);
    float4 l = L4[t];
    float4 us = (reinterpret_cast<const float4*>(uS) + b*(CK/4))[t];
    float4 uh = (reinterpret_cast<const float4*>(uH) + b*(CK/4))[t];
    float zs[4] = { (l.x + gumbelf(us.x))*2.0f, (l.y + gumbelf(us.y))*2.0f,
                    (l.z + gumbelf(us.z))*2.0f, (l.w + gumbelf(us.w))*2.0f };
    float zh[4] = { l.x + gumbelf(uh.x), l.y + gumbelf(uh.y),
                    l.z + gumbelf(uh.z), l.w + gumbelf(uh.w) };
    float vm = fmaxf(fmaxf(zs[0], zs[1]), fmaxf(zs[2], zs[3]));
    #pragma unroll
    for (int o = 16; o; o >>= 1) vm = fmaxf(vm, __shfl_xor_sync(0xffffffffu, vm, o));
    if ((t & 31) == 0) sh[t >> 5] = vm;
    __syncthreads();
    float bm = sh[0];
    #pragma unroll
    for (int i = 1; i < 8; i++) bm = fmaxf(bm, sh[i]);
    float e[4];
    float es = 0.0f;
    #pragma unroll
    for (int j = 0; j < 4; j++) { e[j] = __expf(zs[j] - bm); es += e[j]; }
    #pragma unroll
    for (int o = 16; o; o >>= 1) es += __shfl_xor_sync(0xffffffffu, es, o);
    __syncthreads();
    if ((t & 31) == 0) sh[t >> 5] = es;
    __syncthreads();
    float S = 0.0f;
    #pragma unroll
    for (int i = 0; i < 8; i++) S += sh[i];
    float inv = 1.0f / S;
    L4[t] = make_float4(e[0]*inv, e[1]*inv, e[2]*inv, e[3]*inv);
    float bv = zh[0]; int bi = t*4;
    #pragma unroll
    for (int j = 1; j < 4; j++) if (zh[j] > bv) { bv = zh[j]; bi = t*4 + j; }
    #pragma unroll
    for (int o = 16; o; o >>= 1) {
        float ov = __shfl_xor_sync(0xffffffffu, bv, o);
        int   oi = __shfl_xor_sync(0xffffffffu, bi, o);
        if (ov > bv || (ov == bv && oi < bi)) { bv = ov; bi = oi; }
    }
    if ((t & 31) == 0) { shv[t >> 5] = bv; shi[t >> 5] = bi; }
    __syncthreads();
    if (t == 0 && aOut) {
        float fbv = shv[0]; int fbi = shi[0];
        #pragma unroll
        for (int i = 1; i < 8; i++)
            if (shv[i] > fbv || (shv[i] == fbv && shi[i] < fbi)) { fbv = shv[i]; fbi = shi[i]; }
        aOut[b] = (float)fbi;
    }
}

// merged per-row dot: blocks [0,CB) -> lposN pair, [CB, CB+CK) -> lposK pair
__global__ void k_rowdot2(const float* __restrict__ A1, const float* __restrict__ B1,
                          float* __restrict__ o1,
                          const float* __restrict__ A2, const float* __restrict__ B2,
                          float* __restrict__ o2) {
    int r = blockIdx.x, t = threadIdx.x;  // 32 threads
    const float *Ap, *Bp;
    float* op;
    int rr;
    if (r < CB) { Ap = A1; Bp = B1; op = o1; rr = r; }
    else        { Ap = A2; Bp = B2; op = o2; rr = r - CB; }
    const float4* a4 = reinterpret_cast<const float4*>(Ap) + rr*64;
    const float4* b4 = reinterpret_cast<const float4*>(Bp) + rr*64;
    float4 a = a4[t], b = b4[t];
    float s = a.x*b.x + a.y*b.y + a.z*b.z + a.w*b.w;
    a = a4[t + 32]; b = b4[t + 32];
    s += a.x*b.x + a.y*b.y + a.z*b.z + a.w*b.w;
    #pragma unroll
    for (int o = 16; o; o >>= 1) s += __shfl_xor_sync(0xffffffffu, s, o);
    if (t == 0) op[rr] = s;
}

__device__ __forceinline__ float blockReduceSum1024(float v, float* sh) {
    int t = threadIdx.x;
    #pragma unroll
    for (int o = 16; o; o >>= 1) v += __shfl_xor_sync(0xffffffffu, v, o);
    if ((t & 31) == 0) sh[t >> 5] = v;
    __syncthreads();
    float s = 0.0f;
    if (t < 32) {
        s = sh[t];
        #pragma unroll
        for (int o = 16; o; o >>= 1) s += __shfl_xor_sync(0xffffffffu, s, o);
    }
    return s;
}

__global__ void k_final(const float* __restrict__ pmN, const float* __restrict__ psN,
                        const float* __restrict__ lposN,
                        const float* __restrict__ pmK, const float* __restrict__ psK,
                        const float* __restrict__ lposK,
                        float* __restrict__ outLoss) {
    int t = threadIdx.x;
    __shared__ float sh[32];
    float accN = 0.0f;
    for (int r = t; r < CB; r += 1024) {
        float lp = lposN[r] * INV_TEMP;
        float m = lp, s = 1.0f;
        #pragma unroll
        for (int p = 0; p < PPART; p++) {
            float mp = pmN[r*PPART + p], sp = psN[r*PPART + p];
            float mn = fmaxf(m, mp);
            s = s * __expf(m - mn) + sp * __expf(mp - mn);
            m = mn;
        }
        accN += m + logf(s) - lp;
    }
    float sumN = blockReduceSum1024(accN, sh);
    __syncthreads();
    float accK = 0.0f;
    {
        int r = t;
        float lp = lposK[r] * INV_TEMP;
        float m = lp, s = 1.0f;
        #pragma unroll
        for (int p = 0; p < PPART; p++) {
            float mp = pmK[r*PPART + p], sp = psK[r*PPART + p];
            float mn = fmaxf(m, mp);
            s = s * __expf(m - mn) + sp * __expf(mp - mn);
            m = mn;
        }
        accK = m + logf(s) - lp;
    }
    float sumK = blockReduceSum1024(accK, sh);
    if (t == 0) *outLoss = sumN / (float)CB + sumK / (float)CK;
}

// ------------------------- host launcher (two-view batched schedule) -------------------------
extern "C" void kernel_launch(void* const* d_in, const int* in_sizes, int n_in,
                              void* d_out, int out_size) {
    const float* x1       = (const float*)d_in[0];
    const float* x2       = (const float*)d_in[1];
    const float* W1       = (const float*)d_in[2];
    const float* W2       = (const float*)d_in[3];
    const float* context1 = (const float*)d_in[4];
    const float* context2 = (const float*)d_in[5];
    const float* queue_n  = (const float*)d_in[6];
    const float* queue_k  = (const float*)d_in[7];
    const float* u1a      = (const float*)d_in[8];
    const float* u1b      = (const float*)d_in[9];
    const float* u2a      = (const float*)d_in[10];
    const float* u2b      = (const float*)d_in[11];
    const float* qnoise   = (const float*)d_in[12];

    float* out       = (float*)d_out;
    float* outAssign = out;
    float* outF2     = out + CB;
    float* outAggk2  = outF2 + (size_t)CB*CD;
    float* outLoss   = outAggk2 + (size_t)CK*CD;

    float *pF1, *pL, *pL2, *pAggk1, *pCpart,
          *pLposN, *pLposK, *pPmN, *pPsN, *pPmK, *pPsK;
    __nv_bfloat16 *pXh, *pXl, *pX2h, *pX2l, *pWth, *pWtl, *pWt2h, *pWt2l,
                  *pF1h, *pF1l, *pF2h, *pF2l,
                  *pCtx1h, *pCtx1l, *pCtx2h, *pCtx2l,
                  *pLTh, *pLTl, *pLT2h, *pLT2l, *pFTh, *pFTl, *pFT2h, *pFT2l,
                  *pAggk1b, *pQnb, *pQkb;
    cudaGetSymbolAddress((void**)&pF1,     g_F1);
    cudaGetSymbolAddress((void**)&pL,      g_L);
    cudaGetSymbolAddress((void**)&pL2,     g_L2);
    cudaGetSymbolAddress((void**)&pAggk1,  g_aggk1);
    cudaGetSymbolAddress((void**)&pCpart,  g_Cpart);
    cudaGetSymbolAddress((void**)&pLposN,  g_lposN);
    cudaGetSymbolAddress((void**)&pLposK,  g_lposK);
    cudaGetSymbolAddress((void**)&pPmN,    g_pmN);
    cudaGetSymbolAddress((void**)&pPsN,    g_psN);
    cudaGetSymbolAddress((void**)&pPmK,    g_pmK);
    cudaGetSymbolAddress((void**)&pPsK,    g_psK);
    cudaGetSymbolAddress((void**)&pXh,     g_xh);
    cudaGetSymbolAddress((void**)&pXl,     g_xl);
    cudaGetSymbolAddress((void**)&pX2h,    g_x2h);
    cudaGetSymbolAddress((void**)&pX2l,    g_x2l);
    cudaGetSymbolAddress((void**)&pWth,    g_wth);
    cudaGetSymbolAddress((void**)&pWtl,    g_wtl);
    cudaGetSymbolAddress((void**)&pWt2h,   g_wt2h);
    cudaGetSymbolAddress((void**)&pWt2l,   g_wt2l);
    cudaGetSymbolAddress((void**)&pF1h,    g_F1h);
    cudaGetSymbolAddress((void**)&pF1l,    g_F1l);
    cudaGetSymbolAddress((void**)&pF2h,    g_F2h);
    cudaGetSymbolAddress((void**)&pF2l,    g_F2l);
    cudaGetSymbolAddress((void**)&pCtx1h,  g_ctx1h);
    cudaGetSymbolAddress((void**)&pCtx1l,  g_ctx1l);
    cudaGetSymbolAddress((void**)&pCtx2h,  g_ctx2h);
    cudaGetSymbolAddress((void**)&pCtx2l,  g_ctx2l);
    cudaGetSymbolAddress((void**)&pLTh,    g_LTh);
    cudaGetSymbolAddress((void**)&pLTl,    g_LTl);
    cudaGetSymbolAddress((void**)&pLT2h,   g_LT2h);
    cudaGetSymbolAddress((void**)&pLT2l,   g_LT2l);
    cudaGetSymbolAddress((void**)&pFTh,    g_FTh);
    cudaGetSymbolAddress((void**)&pFTl,    g_FTl);
    cudaGetSymbolAddress((void**)&pFT2h,   g_FT2h);
    cudaGetSymbolAddress((void**)&pFT2l,   g_FT2l);
    cudaGetSymbolAddress((void**)&pAggk1b, g_aggk1b);
    cudaGetSymbolAddress((void**)&pQnb,    g_qnb);
    cudaGetSymbolAddress((void**)&pQkb,    g_qkb);

    cudaFuncSetAttribute(k_lse2, cudaFuncAttributeMaxDynamicSharedMemorySize, LSE_SMEM);
    cudaFuncSetAttribute(k_mma3_b, cudaFuncAttributeMaxDynamicSharedMemorySize, GT_SMEM);

    dim3 t328(32, 8);
    const int MN4_FEAT = CB*CD/4;
    const int MN4_AGG  = CK*CD/4;
    // Cpart layout: feature phase: view1 partials [0, 2*CB*CD), view2 [2*CB*CD, 4*CB*CD)
    //               agg phase:     view1 partials [0, 8*CK*CD), view2 [8*CK*CD, 16*CK*CD)
    float* featC1 = pCpart;
    float* featC2 = pCpart + (size_t)2*CB*CD;
    float* aggC1  = pCpart;
    float* aggC2  = pCpart + (size_t)8*CK*CD;

    // queue prep
    k_l2norm_b<<<CL, 64>>>(queue_n, nullptr, 1, 0, CL, nullptr, pQnb, nullptr,
                           nullptr, nullptr, nullptr);
    k_queue_combine<<<CKQ, 64>>>(queue_k, qnoise, pQkb);

    // weights + inputs split (both views, one launch each)
    k_tsplit_b<<<dim3(CD/32, CDIN/32, 2), t328>>>(W1, pWth, pWtl, W2, pWt2h, pWt2l, CDIN, CD);
    k_split_b<<<2*(CB*CDIN/4/256), 256>>>(x1, pXh, pXl, x2, pX2h, pX2l, CB*CDIN/4);

    // features both views: grid.z = 2 views x ksplit 2
    k_mma3_b<<<dim3(CB/128, CD/128, 4), 256, GT_SMEM>>>(
        pXh, pXl, pWth, pWtl, featC1, pX2h, pX2l, pWt2h, pWt2l, featC2, CB, CD, CDIN, 2);
    k_l2norm_b<<<2*CB, 64>>>(featC1, featC2, 2, MN4_FEAT, CB,
                             pF1, pF1h, pF1l, outF2, pF2h, pF2l);

    // contexts both views
    k_l2norm_b<<<2*CK, 64>>>(context1, context2, 1, 0, CK,
                             nullptr, pCtx1h, pCtx1l, nullptr, pCtx2h, pCtx2l);

    // logits both views (ksplit=1, z=2)
    k_mma3_b<<<dim3(CB/128, CK/128, 2), 256, GT_SMEM>>>(
        pF1h, pF1l, pCtx1h, pCtx1l, pL, pF2h, pF2l, pCtx2h, pCtx2l, pL2, CB, CK, CD, 1);

    // softmax both views
    k_softmax_b<<<2*CB, 256>>>(pL, u1a, u1b, outAssign, pL2, u2a, u2b);

    // transpose-splits for agg (L and F, both views)
    k_tsplit_b<<<dim3(CK/32, CB/32, 2), t328>>>(pL, pLTh, pLTl, pL2, pLT2h, pLT2l, CB, CK);
    k_tsplit_b<<<dim3(CD/32, CB/32, 2), t328>>>(pF1, pFTh, pFTl, outF2, pFT2h, pFT2l, CB, CD);

    // agg both views: grid.z = 2 views x ksplit 8
    k_mma3_b<<<dim3(CK/128, CD/128, 16), 256, GT_SMEM>>>(
        pLTh, pLTl, pFTh, pFTl, aggC1, pLT2h, pLT2l, pFT2h, pFT2l, aggC2, CK, CD, CB, 8);
    k_l2norm_b<<<2*CK, 64>>>(aggC1, aggC2, 8, MN4_AGG, CK,
                             pAggk1, pAggk1b, nullptr, outAggk2, nullptr, nullptr);

    // positives (fp32), merged
    k_rowdot2<<<CB + CK, 32>>>(pF1, outF2, pLposN, pAggk1, outAggk2, pLposK);

    // merged LSE launch: N job (32 x-blocks) + K job (8 x-blocks), y = PSPLIT
    k_lse2<<<dim3(CB/128 + CK/128, PSPLIT), 256, LSE_SMEM>>>(
        pF1h, pQnb, pPmN, pPsN, CL/PSPLIT, CB/128,
        pAggk1b, pQkb, pPmK, pPsK, CKQ/PSPLIT, INV_TEMP);

    // final scalar loss
    k_final<<<1, 1024>>>(pPmN, pPsN, pLposN, pPmK, pPsK, pLposK, outLoss);
}

// round 14
// speedup vs baseline: 2.3060x; 1.0426x over previous
#include <cuda_runtime.h>
#include <cuda_bf16.h>
#include <math.h>
#include <stdint.h>

// Problem constants
#define CB   4096     // batch B
#define CDIN 1024     // D_IN
#define CD   256      // D
#define CK   1024     // K clusters
#define CL   32768    // L queue_n rows
#define CKQ  4096     // K*Q_MULT queue_k rows
#define PSPLIT 8      // j-splits for LSE partials (champion value)
#define PPART (PSPLIT*2)
#define INV_TEMP (1.0f/0.07f)

// ------------------------- scratch (__device__ globals; no runtime alloc) -------------------------
static __device__ __align__(16) float g_F1[CB*CD];
static __device__ __align__(16) float g_L[CB*CK];
static __device__ __align__(16) float g_L2[CB*CK];
static __device__ __align__(16) float g_aggk1[CK*CD];
static __device__ __align__(16) float g_Cpart[8*CB*CD];   // split-K partials (both views)
static __device__ float g_lposN[CB];
static __device__ float g_lposK[CK];
static __device__ float g_pmN[CB*PPART];
static __device__ float g_psN[CB*PPART];
static __device__ float g_pmK[CK*PPART];
static __device__ float g_psK[CK*PPART];
// split-bf16 operand buffers (hi/lo pairs), separate per view for batched launches
static __device__ __align__(16) __nv_bfloat16 g_xh[CB*CDIN],  g_xl[CB*CDIN];
static __device__ __align__(16) __nv_bfloat16 g_x2h[CB*CDIN], g_x2l[CB*CDIN];
static __device__ __align__(16) __nv_bfloat16 g_wth[CD*CDIN], g_wtl[CD*CDIN];
static __device__ __align__(16) __nv_bfloat16 g_wt2h[CD*CDIN],g_wt2l[CD*CDIN];
static __device__ __align__(16) __nv_bfloat16 g_F1h[CB*CD],  g_F1l[CB*CD];
static __device__ __align__(16) __nv_bfloat16 g_F2h[CB*CD],  g_F2l[CB*CD];
static __device__ __align__(16) __nv_bfloat16 g_ctx1h[CK*CD], g_ctx1l[CK*CD];
static __device__ __align__(16) __nv_bfloat16 g_ctx2h[CK*CD], g_ctx2l[CK*CD];
static __device__ __align__(16) __nv_bfloat16 g_LTh[CK*CB],  g_LTl[CK*CB];
static __device__ __align__(16) __nv_bfloat16 g_LT2h[CK*CB], g_LT2l[CK*CB];
static __device__ __align__(16) __nv_bfloat16 g_FTh[CD*CB],  g_FTl[CD*CB];
static __device__ __align__(16) __nv_bfloat16 g_FT2h[CD*CB], g_FT2l[CD*CB];
static __device__ __align__(16) __nv_bfloat16 g_aggk1b[CK*CD];
static __device__ __align__(16) __nv_bfloat16 g_qnb[CL*CD];
static __device__ __align__(16) __nv_bfloat16 g_qkb[CKQ*CD];

// ------------------------- PTX helpers (sm_80-era only: compute_103 virtual arch!) -------------------------
__device__ __forceinline__ uint32_t smem_u32(const void* p) {
    uint32_t a;
    asm("{ .reg .u64 t; cvta.to.shared.u64 t, %1; cvt.u32.u64 %0, t; }" : "=r"(a) : "l"(p));
    return a;
}
__device__ __forceinline__ void cp16(uint32_t dst, const void* src) {
    asm volatile("cp.async.cg.shared.global [%0], [%1], 16;" :: "r"(dst), "l"(src));
}
#define CP_COMMIT() asm volatile("cp.async.commit_group;" ::: "memory")
#define CP_WAIT0()  asm volatile("cp.async.wait_group 0;" ::: "memory")

__device__ __forceinline__ void ldm_x4(uint32_t r[4], uint32_t addr) {
    asm volatile("ldmatrix.sync.aligned.m8n8.x4.shared.b16 {%0,%1,%2,%3}, [%4];"
                 : "=r"(r[0]), "=r"(r[1]), "=r"(r[2]), "=r"(r[3]) : "r"(addr));
}
__device__ __forceinline__ void mma_bf16(float c[4], const uint32_t a[4], uint32_t b0, uint32_t b1) {
    asm volatile("mma.sync.aligned.m16n8k16.row.col.f32.bf16.bf16.f32 "
                 "{%0,%1,%2,%3}, {%4,%5,%6,%7}, {%8,%9}, {%0,%1,%2,%3};"
                 : "+f"(c[0]), "+f"(c[1]), "+f"(c[2]), "+f"(c[3])
                 : "r"(a[0]), "r"(a[1]), "r"(a[2]), "r"(a[3]), "r"(b0), "r"(b1));
}

__device__ __forceinline__ float gumbelf(float u) {
    u = u * (1.0f - 2e-6f) + 1e-6f;
    return -logf(-logf(u));
}
__device__ __forceinline__ void split2(float v, __nv_bfloat16& h, __nv_bfloat16& l) {
    h = __float2bfloat16_rn(v);
    l = __float2bfloat16_rn(v - __bfloat162float(h));
}

// ------------------------- batched split / transpose-split -------------------------
__global__ void k_split_b(const float* __restrict__ in1, __nv_bfloat16* __restrict__ hi1,
                          __nv_bfloat16* __restrict__ lo1,
                          const float* __restrict__ in2, __nv_bfloat16* __restrict__ hi2,
                          __nv_bfloat16* __restrict__ lo2, int n4) {
    int i = blockIdx.x*256 + threadIdx.x;
    const float* in = in1;
    __nv_bfloat16 *hi = hi1, *lo = lo1;
    if (i >= n4) { i -= n4; in = in2; hi = hi2; lo = lo2; }
    float4 v = reinterpret_cast<const float4*>(in)[i];
    __nv_bfloat16 h[4], l[4];
    split2(v.x, h[0], l[0]); split2(v.y, h[1], l[1]);
    split2(v.z, h[2], l[2]); split2(v.w, h[3], l[3]);
    reinterpret_cast<uint2*>(hi)[i] = *reinterpret_cast<uint2*>(h);
    reinterpret_cast<uint2*>(lo)[i] = *reinterpret_cast<uint2*>(l);
}

__global__ void k_tsplit_b(const float* __restrict__ in1, __nv_bfloat16* __restrict__ hiT1,
                           __nv_bfloat16* __restrict__ loT1,
                           const float* __restrict__ in2, __nv_bfloat16* __restrict__ hiT2,
                           __nv_bfloat16* __restrict__ loT2, int R, int C) {
    __shared__ float t[32][33];
    const float* in = blockIdx.z ? in2 : in1;
    __nv_bfloat16* hiT = blockIdx.z ? hiT2 : hiT1;
    __nv_bfloat16* loT = blockIdx.z ? loT2 : loT1;
    int c0 = blockIdx.x*32, r0 = blockIdx.y*32;
    int tx = threadIdx.x, ty = threadIdx.y;  // 32 x 8
    #pragma unroll
    for (int i = 0; i < 4; i++)
        t[ty + i*8][tx] = in[(size_t)(r0 + ty + i*8)*C + c0 + tx];
    __syncthreads();
    #pragma unroll
    for (int i = 0; i < 4; i++) {
        float v = t[tx][ty + i*8];
        __nv_bfloat16 h, l;
        split2(v, h, l);
        size_t o = (size_t)(c0 + ty + i*8)*R + r0 + tx;
        hiT[o] = h; loT[o] = l;
    }
}

// ------------------------- batched row l2norm (D=256) with fused split-K reduce -------------------------
__global__ void k_l2norm_b(const float* __restrict__ in1, const float* __restrict__ in2,
                           int ks, int mn4, int R1,
                           float* __restrict__ outf1, __nv_bfloat16* __restrict__ outhi1,
                           __nv_bfloat16* __restrict__ outlo1,
                           float* __restrict__ outf2, __nv_bfloat16* __restrict__ outhi2,
                           __nv_bfloat16* __restrict__ outlo2) {
    int r = blockIdx.x, t = threadIdx.x;  // 64 threads
    __shared__ float sh[2];
    const float* in = in1;
    float* outf = outf1;
    __nv_bfloat16 *outhi = outhi1, *outlo = outlo1;
    if (r >= R1) { r -= R1; in = in2; outf = outf2; outhi = outhi2; outlo = outlo2; }
    int idx = r*64 + t;
    const float4* p = reinterpret_cast<const float4*>(in);
    float4 v = p[idx];
    for (int z = 1; z < ks; z++) {
        float4 w = p[(size_t)z*mn4 + idx];
        v.x += w.x; v.y += w.y; v.z += w.z; v.w += w.w;
    }
    float ss = v.x*v.x + v.y*v.y + v.z*v.z + v.w*v.w;
    #pragma unroll
    for (int o = 16; o; o >>= 1) ss += __shfl_xor_sync(0xffffffffu, ss, o);
    if ((t & 31) == 0) sh[t >> 5] = ss;
    __syncthreads();
    float s = rsqrtf(fmaxf(sh[0] + sh[1], 1e-12f));
    v.x *= s; v.y *= s; v.z *= s; v.w *= s;
    if (outf) reinterpret_cast<float4*>(outf)[idx] = v;
    if (outhi) {
        __nv_bfloat16 h[4], l[4];
        split2(v.x, h[0], l[0]); split2(v.y, h[1], l[1]);
        split2(v.z, h[2], l[2]); split2(v.w, h[3], l[3]);
        reinterpret_cast<uint2*>(outhi)[idx] = *reinterpret_cast<uint2*>(h);
        if (outlo) reinterpret_cast<uint2*>(outlo)[idx] = *reinterpret_cast<uint2*>(l);
    }
}

// queue = l2norm(2*l2norm(queue_k) + qnoise), fused; plain bf16 output
__global__ void k_queue_combine(const float* __restrict__ qk, const float* __restrict__ noise,
                                __nv_bfloat16* __restrict__ outb) {
    int r = blockIdx.x, t = threadIdx.x;  // 64 threads
    __shared__ float sh[2];
    float4 v = reinterpret_cast<const float4*>(qk)[r*64 + t];
    float ss = v.x*v.x + v.y*v.y + v.z*v.z + v.w*v.w;
    #pragma unroll
    for (int o = 16; o; o >>= 1) ss += __shfl_xor_sync(0xffffffffu, ss, o);
    if ((t & 31) == 0) sh[t >> 5] = ss;
    __syncthreads();
    float s1 = 2.0f * rsqrtf(fmaxf(sh[0] + sh[1], 1e-12f));
    float4 n = reinterpret_cast<const float4*>(noise)[r*64 + t];
    float4 w = make_float4(v.x*s1 + n.x, v.y*s1 + n.y, v.z*s1 + n.z, v.w*s1 + n.w);
    __syncthreads();
    float ss2 = w.x*w.x + w.y*w.y + w.z*w.z + w.w*w.w;
    #pragma unroll
    for (int o = 16; o; o >>= 1) ss2 += __shfl_xor_sync(0xffffffffu, ss2, o);
    if ((t & 31) == 0) sh[t >> 5] = ss2;
    __syncthreads();
    float s2 = rsqrtf(fmaxf(sh[0] + sh[1], 1e-12f));
    w.x *= s2; w.y *= s2; w.z *= s2; w.w *= s2;
    __nv_bfloat162 lo2 = __floats2bfloat162_rn(w.x, w.y);
    __nv_bfloat162 hi2 = __floats2bfloat162_rn(w.z, w.w);
    uint2 u = make_uint2(*(uint32_t*)&lo2, *(uint32_t*)&hi2);
    reinterpret_cast<uint2*>(outb)[r*64 + t] = u;
}

// ------------------------- split-bf16 NT GEMM, two-view batched (validated R13) -------------------------
#define GT_RS    144u
#define GT_TILE  (128u*GT_RS)
#define GT_STAGE (4u*GT_TILE)
#define GT_SMEM  (2u*GT_STAGE)

__device__ __forceinline__ void gt_load(uint32_t dst, const __nv_bfloat16* src,
                                        int row0, int K, int kc) {
    int tid = threadIdx.x;
    #pragma unroll
    for (int i = 0; i < 4; i++) {
        int idx = tid + (i << 8);
        int row = idx >> 3;
        int cc = (idx & 7) << 3;
        cp16(dst + (uint32_t)row*GT_RS + (uint32_t)cc*2u,
             src + (size_t)(row0 + row)*K + kc + cc);
    }
}

__global__ void __launch_bounds__(256, 1) k_mma3_b(
    const __nv_bfloat16* __restrict__ A1h, const __nv_bfloat16* __restrict__ A1l,
    const __nv_bfloat16* __restrict__ B1h, const __nv_bfloat16* __restrict__ B1l,
    float* __restrict__ C1,
    const __nv_bfloat16* __restrict__ A2h, const __nv_bfloat16* __restrict__ A2l,
    const __nv_bfloat16* __restrict__ B2h, const __nv_bfloat16* __restrict__ B2l,
    float* __restrict__ C2,
    int M, int N, int K, int ksplit)
{
    extern __shared__ char sm[];
    uint32_t base = (smem_u32(sm) + 127u) & ~127u;
    int tid = threadIdx.x, lane = tid & 31, w = tid >> 5;
    int mg = w & 3, ng = w >> 2;
    int m0 = blockIdx.x * 128, n0 = blockIdx.y * 128;
    int z = blockIdx.z;
    const __nv_bfloat16 *Ah, *Al, *Bh, *Bl;
    float* Cb;
    if (z < ksplit) { Ah = A1h; Al = A1l; Bh = B1h; Bl = B1l; Cb = C1; }
    else            { Ah = A2h; Al = A2l; Bh = B2h; Bl = B2l; Cb = C2; z -= ksplit; }
    int Klocal = K / ksplit, kbase = z * Klocal;
    float* out = Cb + (size_t)z * M * N;
    int lt = lane >> 3, lr = lane & 7;
    uint32_t aOff = (uint32_t)(mg*32 + (lt & 1)*8 + lr)*GT_RS + (uint32_t)((lt >> 1)*8)*2u;
    uint32_t bOff = (uint32_t)(ng*64 + (lt >> 1)*8 + lr)*GT_RS + (uint32_t)((lt & 1)*8)*2u;

    {
        uint32_t s0 = base;
        gt_load(s0 + 0u*GT_TILE, Ah, m0, K, kbase);
        gt_load(s0 + 1u*GT_TILE, Al, m0, K, kbase);
        gt_load(s0 + 2u*GT_TILE, Bh, n0, K, kbase);
        gt_load(s0 + 3u*GT_TILE, Bl, n0, K, kbase);
        CP_COMMIT();
    }

    float acc[2][8][4];
    #pragma unroll
    for (int mt = 0; mt < 2; mt++)
        #pragma unroll
        for (int nt = 0; nt < 8; nt++)
            #pragma unroll
            for (int c = 0; c < 4; c++) acc[mt][nt][c] = 0.0f;

    int nk = Klocal >> 6;
    for (int kc = 0; kc < nk; kc++) {
        CP_WAIT0();
        __syncthreads();
        if (kc + 1 < nk) {
            uint32_t sn = base + (uint32_t)((kc + 1) & 1)*GT_STAGE;
            int kn = kbase + (kc + 1)*64;
            gt_load(sn + 0u*GT_TILE, Ah, m0, K, kn);
            gt_load(sn + 1u*GT_TILE, Al, m0, K, kn);
            gt_load(sn + 2u*GT_TILE, Bh, n0, K, kn);
            gt_load(sn + 3u*GT_TILE, Bl, n0, K, kn);
            CP_COMMIT();
        }
        uint32_t st = base + (uint32_t)(kc & 1)*GT_STAGE;
        #pragma unroll
        for (int k0 = 0; k0 < 64; k0 += 16) {
            uint32_t a0h[4], a1h[4], a0l[4], a1l[4];
            ldm_x4(a0h, st + 0u*GT_TILE + aOff + (uint32_t)k0*2u);
            ldm_x4(a1h, st + 0u*GT_TILE + aOff + 16u*GT_RS + (uint32_t)k0*2u);
            ldm_x4(a0l, st + 1u*GT_TILE + aOff + (uint32_t)k0*2u);
            ldm_x4(a1l, st + 1u*GT_TILE + aOff + 16u*GT_RS + (uint32_t)k0*2u);
            #pragma unroll
            for (int np = 0; np < 4; np++) {
                uint32_t bh[4], bl[4];
                ldm_x4(bh, st + 2u*GT_TILE + bOff + (uint32_t)np*16u*GT_RS + (uint32_t)k0*2u);
                ldm_x4(bl, st + 3u*GT_TILE + bOff + (uint32_t)np*16u*GT_RS + (uint32_t)k0*2u);
                mma_bf16(acc[0][2*np+0], a0h, bh[0], bh[1]);
                mma_bf16(acc[0][2*np+1], a0h, bh[2], bh[3]);
                mma_bf16(acc[1][2*np+0], a1h, bh[0], bh[1]);
                mma_bf16(acc[1][2*np+1], a1h, bh[2], bh[3]);
                mma_bf16(acc[0][2*np+0], a0h, bl[0], bl[1]);
                mma_bf16(acc[0][2*np+1], a0h, bl[2], bl[3]);
                mma_bf16(acc[1][2*np+0], a1h, bl[0], bl[1]);
                mma_bf16(acc[1][2*np+1], a1h, bl[2], bl[3]);
                mma_bf16(acc[0][2*np+0], a0l, bh[0], bh[1]);
                mma_bf16(acc[0][2*np+1], a0l, bh[2], bh[3]);
                mma_bf16(acc[1][2*np+0], a1l, bh[0], bh[1]);
                mma_bf16(acc[1][2*np+1], a1l, bh[2], bh[3]);
            }
        }
    }

    int gid = lane >> 2, qc = (lane & 3) << 1;
    #pragma unroll
    for (int mt = 0; mt < 2; mt++) {
        #pragma unroll
        for (int nt = 0; nt < 8; nt++) {
            int r0 = m0 + mg*32 + mt*16 + gid;
            int c0 = n0 + ng*64 + nt*8 + qc;
            float2 v0 = make_float2(acc[mt][nt][0], acc[mt][nt][1]);
            float2 v1 = make_float2(acc[mt][nt][2], acc[mt][nt][3]);
            *reinterpret_cast<float2*>(&out[(size_t)r0*N + c0]) = v0;
            *reinterpret_cast<float2*>(&out[(size_t)(r0 + 8)*N + c0]) = v1;
        }
    }
}

// ------------------------- HMMA bf16 LSE, fixed-max epilogue (validated) -------------------------
#define RSB 528u
#define LSE_TILE_BYTES (128u*RSB)
#define LSE_SMEM (3u*LSE_TILE_BYTES + 128u)

__device__ __forceinline__ void lse_load_tile(uint32_t dstbase, const __nv_bfloat16* src) {
    int tid = threadIdx.x;
    #pragma unroll
    for (int i = 0; i < 16; i++) {
        int idx = tid + (i << 8);
        int row = idx >> 5;
        int c = idx & 31;
        cp16(dstbase + (uint32_t)row*RSB + (uint32_t)c*16u, src + row*256 + c*8);
    }
}

__global__ void __launch_bounds__(256, 1) k_lse_mma(
    const __nv_bfloat16* __restrict__ A, const __nv_bfloat16* __restrict__ Q,
    float* __restrict__ pm, float* __restrict__ ps, int jspan, float scale)
{
    extern __shared__ char smem_raw[];
    uint32_t base = (smem_u32(smem_raw) + 127u) & ~127u;
    uint32_t aBase  = base;
    uint32_t qBase0 = base + LSE_TILE_BYTES;
    uint32_t qBase1 = base + 2u*LSE_TILE_BYTES;

    int tid = threadIdx.x;
    int lane = tid & 31, w = tid >> 5;
    int mg = w & 3;
    int ng = w >> 2;
    int m0 = blockIdx.x * 128;
    int jbase = blockIdx.y * jspan;
    int nj = jspan >> 7;

    int lt = lane >> 3, lr = lane & 7;
    uint32_t aAddr = aBase + (uint32_t)(mg*32 + (lt & 1)*8 + lr)*RSB + (uint32_t)((lt >> 1)*8)*2u;
    uint32_t qOff = (uint32_t)(ng*64 + (lt >> 1)*8 + lr)*RSB + (uint32_t)((lt & 1)*8)*2u;

    lse_load_tile(aBase, A + (size_t)m0*256);
    lse_load_tile(qBase0, Q + (size_t)jbase*256);
    CP_COMMIT();

    const float FM = scale;
    float srun[4] = {0.0f, 0.0f, 0.0f, 0.0f};

    for (int jt = 0; jt < nj; jt++) {
        CP_WAIT0();
        __syncthreads();
        if (jt + 1 < nj) {
            lse_load_tile((jt & 1) ? qBase0 : qBase1, Q + (size_t)(jbase + (jt+1)*128)*256);
            CP_COMMIT();
        }
        uint32_t qB = (jt & 1) ? qBase1 : qBase0;

        float acc[2][8][4];
        #pragma unroll
        for (int mt = 0; mt < 2; mt++)
            #pragma unroll
            for (int nt = 0; nt < 8; nt++)
                #pragma unroll
                for (int c = 0; c < 4; c++) acc[mt][nt][c] = 0.0f;

        #pragma unroll 4
        for (int k0 = 0; k0 < 256; k0 += 16) {
            uint32_t a0[4], a1[4];
            ldm_x4(a0, aAddr + (uint32_t)k0*2u);
            ldm_x4(a1, aAddr + 16u*RSB + (uint32_t)k0*2u);
            #pragma unroll
            for (int np = 0; np < 4; np++) {
                uint32_t b[4];
                ldm_x4(b, qB + qOff + (uint32_t)np*16u*RSB + (uint32_t)k0*2u);
                mma_bf16(acc[0][2*np+0], a0, b[0], b[1]);
                mma_bf16(acc[0][2*np+1], a0, b[2], b[3]);
                mma_bf16(acc[1][2*np+0], a1, b[0], b[1]);
                mma_bf16(acc[1][2*np+1], a1, b[2], b[3]);
            }
        }

        // fixed-max epilogue
        #pragma unroll
        for (int mt = 0; mt < 2; mt++) {
            #pragma unroll
            for (int rh = 0; rh < 2; rh++) {
                int s = mt*2 + rh;
                float es = 0.0f;
                #pragma unroll
                for (int nt = 0; nt < 8; nt++) {
                    es += __expf(fmaf(acc[mt][nt][rh*2+0], scale, -FM));
                    es += __expf(fmaf(acc[mt][nt][rh*2+1], scale, -FM));
                }
                srun[s] += es;
            }
        }
    }

    #pragma unroll
    for (int s = 0; s < 4; s++) {
        srun[s] += __shfl_xor_sync(0xffffffffu, srun[s], 1);
        srun[s] += __shfl_xor_sync(0xffffffffu, srun[s], 2);
    }
    if ((lane & 3) == 0) {
        int gid = lane >> 2;
        int slot = blockIdx.y*2 + ng;
        #pragma unroll
        for (int mt = 0; mt < 2; mt++) {
            #pragma unroll
            for (int rh = 0; rh < 2; rh++) {
                int s = mt*2 + rh;
                int row = m0 + mg*32 + mt*16 + rh*8 + gid;
                pm[row*PPART + slot] = FM;
                ps[row*PPART + slot] = srun[s];
            }
        }
    }
}

// ------------------------- batched gumbel-softmax (both views, one launch) -------------------------
__global__ void k_softmax_b(float* __restrict__ L1, const float* __restrict__ u1S,
                            const float* __restrict__ u1H, float* __restrict__ assignOut,
                            float* __restrict__ L2v, const float* __restrict__ u2S,
                            const float* __restrict__ u2H) {
    int b = blockIdx.x, t = threadIdx.x;
    float* Lm;
    const float *uS, *uH;
    float* aOut;
    if (b < CB) { Lm = L1; uS = u1S; uH = u1H; aOut = assignOut; }
    else        { b -= CB; Lm = L2v; uS = u2S; uH = u2H; aOut = nullptr; }
    __shared__ float sh[8];
    __shared__ float shv[8];
    __shared__ int shi[8];
    float4* L4 = reinterpret_cast<float4*>(Lm) + b*(CK/4);
    float4 l = L4[t];
    float4 us = (reinterpret_cast<const float4*>(uS) + b*(CK/4))[t];
    float4 uh = (reinterpret_cast<const float4*>(uH) + b*(CK/4))[t];
    float zs[4] = { (l.x + gumbelf(us.x))*2.0f, (l.y + gumbelf(us.y))*2.0f,
                    (l.z + gumbelf(us.z))*2.0f, (l.w + gumbelf(us.w))*2.0f };
    float zh[4] = { l.x + gumbelf(uh.x), l.y + gumbelf(uh.y),
                    l.z + gumbelf(uh.z), l.w + gumbelf(uh.w) };
    float vm = fmaxf(fmaxf(zs[0], zs[1]), fmaxf(zs[2], zs[3]));
    #pragma unroll
    for (int o = 16; o; o >>= 1) vm = fmaxf(vm, __shfl_xor_sync(0xffffffffu, vm, o));
    if ((t & 31) == 0) sh[t >> 5] = vm;
    __syncthreads();
    float bm = sh[0];
    #pragma unroll
    for (int i = 1; i < 8; i++) bm = fmaxf(bm, sh[i]);
    float e[4];
    float es = 0.0f;
    #pragma unroll
    for (int j = 0; j < 4; j++) { e[j] = __expf(zs[j] - bm); es += e[j]; }
    #pragma unroll
    for (int o = 16; o; o >>= 1) es += __shfl_xor_sync(0xffffffffu, es, o);
    __syncthreads();
    if ((t & 31) == 0) sh[t >> 5] = es;
    __syncthreads();
    float S = 0.0f;
    #pragma unroll
    for (int i = 0; i < 8; i++) S += sh[i];
    float inv = 1.0f / S;
    L4[t] = make_float4(e[0]*inv, e[1]*inv, e[2]*inv, e[3]*inv);
    float bv = zh[0]; int bi = t*4;
    #pragma unroll
    for (int j = 1; j < 4; j++) if (zh[j] > bv) { bv = zh[j]; bi = t*4 + j; }
    #pragma unroll
    for (int o = 16; o; o >>= 1) {
        float ov = __shfl_xor_sync(0xffffffffu, bv, o);
        int   oi = __shfl_xor_sync(0xffffffffu, bi, o);
        if (ov > bv || (ov == bv && oi < bi)) { bv = ov; bi = oi; }
    }
    if ((t & 31) == 0) { shv[t >> 5] = bv; shi[t >> 5] = bi; }
    __syncthreads();
    if (t == 0 && aOut) {
        float fbv = shv[0]; int fbi = shi[0];
        #pragma unroll
        for (int i = 1; i < 8; i++)
            if (shv[i] > fbv || (shv[i] == fbv && shi[i] < fbi)) { fbv = shv[i]; fbi = shi[i]; }
        aOut[b] = (float)fbi;
    }
}

// merged per-row dot
__global__ void k_rowdot2(const float* __restrict__ A1, const float* __restrict__ B1,
                          float* __restrict__ o1,
                          const float* __restrict__ A2, const float* __restrict__ B2,
                          float* __restrict__ o2) {
    int r = blockIdx.x, t = threadIdx.x;  // 32 threads
    const float *Ap, *Bp;
    float* op;
    int rr;
    if (r < CB) { Ap = A1; Bp = B1; op = o1; rr = r; }
    else        { Ap = A2; Bp = B2; op = o2; rr = r - CB; }
    const float4* a4 = reinterpret_cast<const float4*>(Ap) + rr*64;
    const float4* b4 = reinterpret_cast<const float4*>(Bp) + rr*64;
    float4 a = a4[t], b = b4[t];
    float s = a.x*b.x + a.y*b.y + a.z*b.z + a.w*b.w;
    a = a4[t + 32]; b = b4[t + 32];
    s += a.x*b.x + a.y*b.y + a.z*b.z + a.w*b.w;
    #pragma unroll
    for (int o = 16; o; o >>= 1) s += __shfl_xor_sync(0xffffffffu, s, o);
    if (t == 0) op[rr] = s;
}

__device__ __forceinline__ float blockReduceSum1024(float v, float* sh) {
    int t = threadIdx.x;
    #pragma unroll
    for (int o = 16; o; o >>= 1) v += __shfl_xor_sync(0xffffffffu, v, o);
    if ((t & 31) == 0) sh[t >> 5] = v;
    __syncthreads();
    float s = 0.0f;
    if (t < 32) {
        s = sh[t];
        #pragma unroll
        for (int o = 16; o; o >>= 1) s += __shfl_xor_sync(0xffffffffu, s, o);
    }
    return s;
}

__global__ void k_final(const float* __restrict__ pmN, const float* __restrict__ psN,
                        const float* __restrict__ lposN,
                        const float* __restrict__ pmK, const float* __restrict__ psK,
                        const float* __restrict__ lposK,
                        float* __restrict__ outLoss) {
    int t = threadIdx.x;
    __shared__ float sh[32];
    float accN = 0.0f;
    for (int r = t; r < CB; r += 1024) {
        float lp = lposN[r] * INV_TEMP;
        float m = lp, s = 1.0f;
        #pragma unroll
        for (int p = 0; p < PPART; p++) {
            float mp = pmN[r*PPART + p], sp = psN[r*PPART + p];
            float mn = fmaxf(m, mp);
            s = s * __expf(m - mn) + sp * __expf(mp - mn);
            m = mn;
        }
        accN += m + logf(s) - lp;
    }
    float sumN = blockReduceSum1024(accN, sh);
    __syncthreads();
    float accK = 0.0f;
    {
        int r = t;
        float lp = lposK[r] * INV_TEMP;
        float m = lp, s = 1.0f;
        #pragma unroll
        for (int p = 0; p < PPART; p++) {
            float mp = pmK[r*PPART + p], sp = psK[r*PPART + p];
            float mn = fmaxf(m, mp);
            s = s * __expf(m - mn) + sp * __expf(mp - mn);
            m = mn;
        }
        accK = m + logf(s) - lp;
    }
    float sumK = blockReduceSum1024(accK, sh);
    if (t == 0) *outLoss = sumN / (float)CB + sumK / (float)CK;
}

// ------------------------- host launcher (R13 batched schedule + single LSE-N fork) -------------------------
extern "C" void kernel_launch(void* const* d_in, const int* in_sizes, int n_in,
                              void* d_out, int out_size) {
    const float* x1       = (const float*)d_in[0];
    const float* x2       = (const float*)d_in[1];
    const float* W1       = (const float*)d_in[2];
    const float* W2       = (const float*)d_in[3];
    const float* context1 = (const float*)d_in[4];
    const float* context2 = (const float*)d_in[5];
    const float* queue_n  = (const float*)d_in[6];
    const float* queue_k  = (const float*)d_in[7];
    const float* u1a      = (const float*)d_in[8];
    const float* u1b      = (const float*)d_in[9];
    const float* u2a      = (const float*)d_in[10];
    const float* u2b      = (const float*)d_in[11];
    const float* qnoise   = (const float*)d_in[12];

    float* out       = (float*)d_out;
    float* outAssign = out;
    float* outF2     = out + CB;
    float* outAggk2  = outF2 + (size_t)CB*CD;
    float* outLoss   = outAggk2 + (size_t)CK*CD;

    float *pF1, *pL, *pL2, *pAggk1, *pCpart,
          *pLposN, *pLposK, *pPmN, *pPsN, *pPmK, *pPsK;
    __nv_bfloat16 *pXh, *pXl, *pX2h, *pX2l, *pWth, *pWtl, *pWt2h, *pWt2l,
                  *pF1h, *pF1l, *pF2h, *pF2l,
                  *pCtx1h, *pCtx1l, *pCtx2h, *pCtx2l,
                  *pLTh, *pLTl, *pLT2h, *pLT2l, *pFTh, *pFTl, *pFT2h, *pFT2l,
                  *pAggk1b, *pQnb, *pQkb;
    cudaGetSymbolAddress((void**)&pF1,     g_F1);
    cudaGetSymbolAddress((void**)&pL,      g_L);
    cudaGetSymbolAddress((void**)&pL2,     g_L2);
    cudaGetSymbolAddress((void**)&pAggk1,  g_aggk1);
    cudaGetSymbolAddress((void**)&pCpart,  g_Cpart);
    cudaGetSymbolAddress((void**)&pLposN,  g_lposN);
    cudaGetSymbolAddress((void**)&pLposK,  g_lposK);
    cudaGetSymbolAddress((void**)&pPmN,    g_pmN);
    cudaGetSymbolAddress((void**)&pPsN,    g_psN);
    cudaGetSymbolAddress((void**)&pPmK,    g_pmK);
    cudaGetSymbolAddress((void**)&pPsK,    g_psK);
    cudaGetSymbolAddress((void**)&pXh,     g_xh);
    cudaGetSymbolAddress((void**)&pXl,     g_xl);
    cudaGetSymbolAddress((void**)&pX2h,    g_x2h);
    cudaGetSymbolAddress((void**)&pX2l,    g_x2l);
    cudaGetSymbolAddress((void**)&pWth,    g_wth);
    cudaGetSymbolAddress((void**)&pWtl,    g_wtl);
    cudaGetSymbolAddress((void**)&pWt2h,   g_wt2h);
    cudaGetSymbolAddress((void**)&pWt2l,   g_wt2l);
    cudaGetSymbolAddress((void**)&pF1h,    g_F1h);
    cudaGetSymbolAddress((void**)&pF1l,    g_F1l);
    cudaGetSymbolAddress((void**)&pF2h,    g_F2h);
    cudaGetSymbolAddress((void**)&pF2l,    g_F2l);
    cudaGetSymbolAddress((void**)&pCtx1h,  g_ctx1h);
    cudaGetSymbolAddress((void**)&pCtx1l,  g_ctx1l);
    cudaGetSymbolAddress((void**)&pCtx2h,  g_ctx2h);
    cudaGetSymbolAddress((void**)&pCtx2l,  g_ctx2l);
    cudaGetSymbolAddress((void**)&pLTh,    g_LTh);
    cudaGetSymbolAddress((void**)&pLTl,    g_LTl);
    cudaGetSymbolAddress((void**)&pLT2h,   g_LT2h);
    cudaGetSymbolAddress((void**)&pLT2l,   g_LT2l);
    cudaGetSymbolAddress((void**)&pFTh,    g_FTh);
    cudaGetSymbolAddress((void**)&pFTl,    g_FTl);
    cudaGetSymbolAddress((void**)&pFT2h,   g_FT2h);
    cudaGetSymbolAddress((void**)&pFT2l,   g_FT2l);
    cudaGetSymbolAddress((void**)&pAggk1b, g_aggk1b);
    cudaGetSymbolAddress((void**)&pQnb,    g_qnb);
    cudaGetSymbolAddress((void**)&pQkb,    g_qkb);

    // stream/events created once (host-side resources only; identical graph every call)
    static cudaStream_t s2 = 0;
    static cudaEvent_t eF, eN;
    static bool inited = false;
    if (!inited) {
        cudaStreamCreateWithFlags(&s2, cudaStreamNonBlocking);
        cudaEventCreateWithFlags(&eF, cudaEventDisableTiming);
        cudaEventCreateWithFlags(&eN, cudaEventDisableTiming);
        cudaFuncSetAttribute(k_lse_mma, cudaFuncAttributeMaxDynamicSharedMemorySize, LSE_SMEM);
        cudaFuncSetAttribute(k_mma3_b, cudaFuncAttributeMaxDynamicSharedMemorySize, GT_SMEM);
        inited = true;
    }

    dim3 t328(32, 8);
    const int MN4_FEAT = CB*CD/4;
    const int MN4_AGG  = CK*CD/4;
    float* featC1 = pCpart;
    float* featC2 = pCpart + (size_t)2*CB*CD;
    float* aggC1  = pCpart;
    float* aggC2  = pCpart + (size_t)8*CK*CD;

    // queue prep (main stream, before eF so the fork covers it)
    k_l2norm_b<<<CL, 64>>>(queue_n, nullptr, 1, 0, CL, nullptr, pQnb, nullptr,
                           nullptr, nullptr, nullptr);
    k_queue_combine<<<CKQ, 64>>>(queue_k, qnoise, pQkb);

    // weights + inputs split (both views)
    k_tsplit_b<<<dim3(CD/32, CDIN/32, 2), t328>>>(W1, pWth, pWtl, W2, pWt2h, pWt2l, CDIN, CD);
    k_split_b<<<2*(CB*CDIN/4/256), 256>>>(x1, pXh, pXl, x2, pX2h, pX2l, CB*CDIN/4);

    // features both views
    k_mma3_b<<<dim3(CB/128, CD/128, 4), 256, GT_SMEM>>>(
        pXh, pXl, pWth, pWtl, featC1, pX2h, pX2l, pWt2h, pWt2l, featC2, CB, CD, CDIN, 2);
    k_l2norm_b<<<2*CB, 64>>>(featC1, featC2, 2, MN4_FEAT, CB,
                             pF1, pF1h, pF1l, outF2, pF2h, pF2l);
    cudaEventRecord(eF, 0);

    // ---- fork: LSE-N on s2 (needs only F1h + qnb) ----
    cudaStreamWaitEvent(s2, eF, 0);
    k_lse_mma<<<dim3(CB/128, PSPLIT), 256, LSE_SMEM, s2>>>(pF1h, pQnb, pPmN, pPsN, CL/PSPLIT, INV_TEMP);
    cudaEventRecord(eN, s2);

    // ---- main: logits -> softmax -> agg chain (independent of LSE-N) ----
    k_l2norm_b<<<2*CK, 64>>>(context1, context2, 1, 0, CK,
                             nullptr, pCtx1h, pCtx1l, nullptr, pCtx2h, pCtx2l);
    k_mma3_b<<<dim3(CB/128, CK/128, 2), 256, GT_SMEM>>>(
        pF1h, pF1l, pCtx1h, pCtx1l, pL, pF2h, pF2l, pCtx2h, pCtx2l, pL2, CB, CK, CD, 1);
    k_softmax_b<<<2*CB, 256>>>(pL, u1a, u1b, outAssign, pL2, u2a, u2b);
    k_tsplit_b<<<dim3(CK/32, CB/32, 2), t328>>>(pL, pLTh, pLTl, pL2, pLT2h, pLT2l, CB, CK);
    k_tsplit_b<<<dim3(CD/32, CB/32, 2), t328>>>(pF1, pFTh, pFTl, outF2, pFT2h, pFT2l, CB, CD);
    k_mma3_b<<<dim3(CK/128, CD/128, 16), 256, GT_SMEM>>>(
        pLTh, pLTl, pFTh, pFTl, aggC1, pLT2h, pLT2l, pFT2h, pFT2l, aggC2, CK, CD, CB, 8);
    k_l2norm_b<<<2*CK, 64>>>(aggC1, aggC2, 8, MN4_AGG, CK,
                             pAggk1, pAggk1b, nullptr, outAggk2, nullptr, nullptr);

    // positives
    k_rowdot2<<<CB + CK, 32>>>(pF1, outF2, pLposN, pAggk1, outAggk2, pLposK);

    // LSE-K on main
    k_lse_mma<<<dim3(CK/128, PSPLIT), 256, LSE_SMEM>>>(pAggk1b, pQkb, pPmK, pPsK, CKQ/PSPLIT, INV_TEMP);

    // join + final scalar loss
    cudaStreamWaitEvent(0, eN, 0);
    k_final<<<1, 1024>>>(pPmN, pPsN, pLposN, pPmK, pPsK, pLposK, outLoss);
}